// round 1
// baseline (speedup 1.0000x reference)
#include <cuda_runtime.h>
#include <math.h>
#include <float.h>

#define NN      65536
#define NGRAPH  64
#define GN      1024
#define DIM     128
#define EDGES   2097152
#define FK      4
#define FEDGES  (NN*FK)

// ---------------- scratch (no allocations allowed) ----------------
__device__ float S_xn[NN*DIM];
__device__ float S_hf[NN*DIM];
__device__ float S_hs[NN*DIM];
__device__ float S_feat[NN*DIM];
__device__ float S_stru[NN*DIM];
__device__ int   S_fdst[FEDGES];
__device__ int   S_cnt_s[NN], S_off_s[NN], S_cur_s[NN];
__device__ int   S_cnt_f[NN], S_off_f[NN], S_cur_f[NN];
__device__ float S_dinv_s[NN], S_dinv_f[NN];
__device__ int   S_csr_s[EDGES];
__device__ int   S_csr_f[FEDGES];

// ---------------- small helpers ----------------
__device__ __forceinline__ bool cand_better(float da, int ja, float db, int jb) {
    // "farther" = smaller dot; tie -> smaller index (top_k tie rule)
    return (da < db) || (da == db && ja < jb);
}

// ---------------- 0: zero degree counters ----------------
__global__ void zero_counts_kernel() {
    int i = blockIdx.x * blockDim.x + threadIdx.x;
    if (i < NN) { S_cnt_s[i] = 0; S_cnt_f[i] = 0; }
}

// ---------------- 1: structural in-degree ----------------
__global__ void count_stru_kernel(const int* __restrict__ dst) {
    int e = blockIdx.x * blockDim.x + threadIdx.x;
    if (e < EDGES) atomicAdd(&S_cnt_s[dst[e]], 1);
}

// ---------------- 2: row-normalize x ----------------
__global__ void normalize_kernel(const float* __restrict__ X) {
    int w = (blockIdx.x * blockDim.x + threadIdx.x) >> 5;
    int l = threadIdx.x & 31;
    if (w >= NN) return;
    float4 v = *(const float4*)(X + (size_t)w * DIM + l * 4);
    float ss = v.x*v.x + v.y*v.y + v.z*v.z + v.w*v.w;
    #pragma unroll
    for (int o = 16; o > 0; o >>= 1) ss += __shfl_xor_sync(0xffffffffu, ss, o);
    float nrm = sqrtf(ss);
    float inv = 1.0f / fmaxf(nrm, 1e-8f);
    float4 o4 = make_float4(v.x*inv, v.y*inv, v.z*inv, v.w*inv);
    *(float4*)(S_xn + (size_t)w * DIM + l * 4) = o4;
}

// ---------------- 3: distance GEMM + top-4 farthest ----------------
// grid: 64 graphs * 16 i-tiles of 64 rows. block 256 threads.
// smem (dynamic): sI[128][68] (d-major), sJ[128][68], cand dot[64][64], cand idx[64][64]
#define TOPK_SMEM ((128*68*2 + 64*64)*4 + 64*64*4)
__global__ void topk_kernel(int* __restrict__ fdst_unused /*unused, use global*/) {
    extern __shared__ float sm[];
    float* sI = sm;
    float* sJ = sm + 128*68;
    float* cD = sJ + 128*68;
    int*   cJ = (int*)(cD + 64*64);

    int t  = threadIdx.x;
    int g  = blockIdx.x >> 4;
    int it = blockIdx.x & 15;
    int i0 = it * 64;
    const float* xg = S_xn + (size_t)g * GN * DIM;

    // load i-tile transposed: sI[d][i]
    for (int q = t; q < 64*32; q += 256) {
        int row = q >> 5, ch = q & 31;
        float4 v = *(const float4*)(xg + (size_t)(i0 + row) * DIM + ch * 4);
        sI[(ch*4+0)*68 + row] = v.x;
        sI[(ch*4+1)*68 + row] = v.y;
        sI[(ch*4+2)*68 + row] = v.z;
        sI[(ch*4+3)*68 + row] = v.w;
    }

    int ti = t >> 4, tj = t & 15;
    float t4d[4][4];
    int   t4i[4][4];
    #pragma unroll
    for (int m = 0; m < 4; m++)
        #pragma unroll
        for (int r = 0; r < 4; r++) { t4d[m][r] = FLT_MAX; t4i[m][r] = 0x7fffffff; }

    for (int cj = 0; cj < 16; cj++) {
        __syncthreads();
        for (int q = t; q < 64*32; q += 256) {
            int row = q >> 5, ch = q & 31;
            float4 v = *(const float4*)(xg + (size_t)(cj*64 + row) * DIM + ch * 4);
            sJ[(ch*4+0)*68 + row] = v.x;
            sJ[(ch*4+1)*68 + row] = v.y;
            sJ[(ch*4+2)*68 + row] = v.z;
            sJ[(ch*4+3)*68 + row] = v.w;
        }
        __syncthreads();

        float acc[4][4];
        #pragma unroll
        for (int m = 0; m < 4; m++)
            #pragma unroll
            for (int n = 0; n < 4; n++) acc[m][n] = 0.f;

        #pragma unroll 4
        for (int d = 0; d < 128; d++) {
            float4 a = *(const float4*)(sI + d*68 + ti*4);
            float4 b = *(const float4*)(sJ + d*68 + tj*4);
            float av[4] = {a.x, a.y, a.z, a.w};
            float bv[4] = {b.x, b.y, b.z, b.w};
            #pragma unroll
            for (int m = 0; m < 4; m++)
                #pragma unroll
                for (int n = 0; n < 4; n++) acc[m][n] += av[m] * bv[n];
        }

        #pragma unroll
        for (int m = 0; m < 4; m++) {
            #pragma unroll
            for (int n = 0; n < 4; n++) {
                float dv = acc[m][n];
                int jl = cj*64 + tj*4 + n;
                if (cand_better(dv, jl, t4d[m][3], t4i[m][3])) {
                    t4d[m][3] = dv; t4i[m][3] = jl;
                    #pragma unroll
                    for (int r = 3; r >= 1; r--) {
                        if (cand_better(t4d[m][r], t4i[m][r], t4d[m][r-1], t4i[m][r-1])) {
                            float td = t4d[m][r]; t4d[m][r] = t4d[m][r-1]; t4d[m][r-1] = td;
                            int   tt = t4i[m][r]; t4i[m][r] = t4i[m][r-1]; t4i[m][r-1] = tt;
                        }
                    }
                }
            }
        }
    }
    __syncthreads();
    #pragma unroll
    for (int m = 0; m < 4; m++) {
        int row = ti*4 + m;
        #pragma unroll
        for (int r = 0; r < 4; r++) {
            cD[row*64 + tj*4 + r] = t4d[m][r];
            cJ[row*64 + tj*4 + r] = t4i[m][r];
        }
    }
    __syncthreads();
    if (t < 64) {
        float bd[4]; int bi[4];
        #pragma unroll
        for (int r = 0; r < 4; r++) { bd[r] = FLT_MAX; bi[r] = 0x7fffffff; }
        for (int c = 0; c < 64; c++) {
            float dv = cD[t*64 + c];
            int   jl = cJ[t*64 + c];
            if (cand_better(dv, jl, bd[3], bi[3])) {
                bd[3] = dv; bi[3] = jl;
                #pragma unroll
                for (int r = 3; r >= 1; r--) {
                    if (cand_better(bd[r], bi[r], bd[r-1], bi[r-1])) {
                        float td = bd[r]; bd[r] = bd[r-1]; bd[r-1] = td;
                        int   tt = bi[r]; bi[r] = bi[r-1]; bi[r-1] = tt;
                    }
                }
            }
        }
        int gi = g*GN + i0 + t;
        #pragma unroll
        for (int r = 0; r < 4; r++) {
            int dg = g*GN + bi[r];
            S_fdst[gi*4 + r] = dg;
            atomicAdd(&S_cnt_f[dg], 1);
        }
    }
}

// ---------------- 4: H = X @ W  (K = DIM = 128) ----------------
#define GEMM_SMEM ((16384 + 128*68)*4)
__global__ void gemm128_kernel(const float* __restrict__ X, const float* __restrict__ W,
                               float* __restrict__ H) {
    extern __shared__ float sm[];
    float* sW = sm;            // [128][128]
    float* sX = sm + 16384;    // [128][68] d-major
    int t = threadIdx.x;
    int r0 = blockIdx.x * 64;

    for (int q = t; q < 4096; q += 256) ((float4*)sW)[q] = ((const float4*)W)[q];
    for (int q = t; q < 2048; q += 256) {
        int row = q >> 5, ch = q & 31;
        float4 v = *(const float4*)(X + (size_t)(r0 + row) * DIM + ch * 4);
        sX[(ch*4+0)*68 + row] = v.x;
        sX[(ch*4+1)*68 + row] = v.y;
        sX[(ch*4+2)*68 + row] = v.z;
        sX[(ch*4+3)*68 + row] = v.w;
    }
    __syncthreads();

    int tr = t >> 4, tc = t & 15;   // rows tr*4+m, cols tc*8+n
    float acc[4][8];
    #pragma unroll
    for (int m = 0; m < 4; m++)
        #pragma unroll
        for (int n = 0; n < 8; n++) acc[m][n] = 0.f;

    #pragma unroll 4
    for (int k = 0; k < 128; k++) {
        float4 a  = *(const float4*)(sX + k*68 + tr*4);
        float4 b0 = *(const float4*)(sW + k*128 + tc*8);
        float4 b1 = *(const float4*)(sW + k*128 + tc*8 + 4);
        float av[4] = {a.x, a.y, a.z, a.w};
        float bv[8] = {b0.x, b0.y, b0.z, b0.w, b1.x, b1.y, b1.z, b1.w};
        #pragma unroll
        for (int m = 0; m < 4; m++)
            #pragma unroll
            for (int n = 0; n < 8; n++) acc[m][n] += av[m] * bv[n];
    }
    #pragma unroll
    for (int m = 0; m < 4; m++) {
        int row = r0 + tr*4 + m;
        #pragma unroll
        for (int n = 0; n < 8; n += 4) {
            float4 o4 = make_float4(acc[m][n], acc[m][n+1], acc[m][n+2], acc[m][n+3]);
            *(float4*)(H + (size_t)row * DIM + tc*8 + n) = o4;
        }
    }
}

// ---------------- 5: exclusive scan (one block, 1024 threads, n=65536) ----------------
__global__ void scan_kernel(const int* __restrict__ cnt, int* __restrict__ off,
                            int* __restrict__ cur) {
    __shared__ int wsum[32];
    int t = threadIdx.x;
    int base = t * 64;
    int s = 0;
    for (int i = 0; i < 64; i++) s += cnt[base + i];
    int lane = t & 31, wid = t >> 5;
    int v = s;
    #pragma unroll
    for (int o = 1; o < 32; o <<= 1) {
        int u = __shfl_up_sync(0xffffffffu, v, o);
        if (lane >= o) v += u;
    }
    if (lane == 31) wsum[wid] = v;
    __syncthreads();
    if (wid == 0) {
        int w = wsum[lane];
        #pragma unroll
        for (int o = 1; o < 32; o <<= 1) {
            int u = __shfl_up_sync(0xffffffffu, w, o);
            if (lane >= o) w += u;
        }
        wsum[lane] = w;
    }
    __syncthreads();
    int excl = v - s + (wid > 0 ? wsum[wid - 1] : 0);
    int run = excl;
    for (int i = 0; i < 64; i++) {
        off[base + i] = run;
        cur[base + i] = run;
        run += cnt[base + i];
    }
}

// ---------------- 6: scatter to CSR ----------------
__global__ void scatter_stru_kernel(const int* __restrict__ src, const int* __restrict__ dst) {
    int e = blockIdx.x * blockDim.x + threadIdx.x;
    if (e < EDGES) {
        int d = dst[e];
        int p = atomicAdd(&S_cur_s[d], 1);
        S_csr_s[p] = src[e];
    }
}
__global__ void scatter_feat_kernel() {
    int e = blockIdx.x * blockDim.x + threadIdx.x;
    if (e < FEDGES) {
        int d = S_fdst[e];
        int p = atomicAdd(&S_cur_f[d], 1);
        S_csr_f[p] = e >> 2;   // src node
    }
}

// ---------------- 7: dinv = rsqrt(indeg + 1) ----------------
__global__ void dinv_kernel() {
    int i = blockIdx.x * blockDim.x + threadIdx.x;
    if (i < NN) {
        S_dinv_s[i] = rsqrtf((float)(S_cnt_s[i] + 1));
        S_dinv_f[i] = rsqrtf((float)(S_cnt_f[i] + 1));
    }
}

// ---------------- 8: aggregate + bias + relu + LN (warp per node) ----------------
__global__ void agg_ln_kernel(const float* __restrict__ H, const int* __restrict__ csr,
                              const int* __restrict__ off, const int* __restrict__ cnt,
                              const float* __restrict__ dinv,
                              const float* __restrict__ bias, const float* __restrict__ gamma,
                              const float* __restrict__ beta, float* __restrict__ out) {
    int w = (blockIdx.x * blockDim.x + threadIdx.x) >> 5;
    int l = threadIdx.x & 31;
    if (w >= NN) return;
    float dv = dinv[w];
    float4 hv = *(const float4*)(H + (size_t)w * DIM + l * 4);
    float sw = dv * dv;
    float4 acc = make_float4(hv.x*sw, hv.y*sw, hv.z*sw, hv.w*sw);
    int base = off[w], n = cnt[w];
    int e = 0;
    for (; e + 1 < n; e += 2) {
        int s0 = csr[base + e], s1 = csr[base + e + 1];
        float w0 = dinv[s0] * dv, w1 = dinv[s1] * dv;
        float4 h0 = *(const float4*)(H + (size_t)s0 * DIM + l * 4);
        float4 h1 = *(const float4*)(H + (size_t)s1 * DIM + l * 4);
        acc.x += w0*h0.x + w1*h1.x;
        acc.y += w0*h0.y + w1*h1.y;
        acc.z += w0*h0.z + w1*h1.z;
        acc.w += w0*h0.w + w1*h1.w;
    }
    if (e < n) {
        int s0 = csr[base + e];
        float w0 = dinv[s0] * dv;
        float4 h0 = *(const float4*)(H + (size_t)s0 * DIM + l * 4);
        acc.x += w0*h0.x; acc.y += w0*h0.y; acc.z += w0*h0.z; acc.w += w0*h0.w;
    }
    float4 bb = *(const float4*)(bias + l * 4);
    float v0 = fmaxf(acc.x + bb.x, 0.f);
    float v1 = fmaxf(acc.y + bb.y, 0.f);
    float v2 = fmaxf(acc.z + bb.z, 0.f);
    float v3 = fmaxf(acc.w + bb.w, 0.f);
    float s1 = v0 + v1 + v2 + v3;
    #pragma unroll
    for (int o = 16; o > 0; o >>= 1) s1 += __shfl_xor_sync(0xffffffffu, s1, o);
    float mean = s1 * (1.0f / 128.0f);
    float d0 = v0 - mean, d1 = v1 - mean, d2 = v2 - mean, d3 = v3 - mean;
    float q = d0*d0 + d1*d1 + d2*d2 + d3*d3;
    #pragma unroll
    for (int o = 16; o > 0; o >>= 1) q += __shfl_xor_sync(0xffffffffu, q, o);
    float rstd = rsqrtf(q * (1.0f / 128.0f) + 1e-5f);
    float4 gg = *(const float4*)(gamma + l * 4);
    float4 be = *(const float4*)(beta + l * 4);
    float4 o4 = make_float4(d0*rstd*gg.x + be.x, d1*rstd*gg.y + be.y,
                            d2*rstd*gg.z + be.z, d3*rstd*gg.w + be.w);
    *(float4*)(out + (size_t)w * DIM + l * 4) = o4;
}

// ---------------- 9: gate GEMM + sigmoid + fuse + LN + residual ----------------
#define GATE_SMEM ((32768 + 256*36 + 32*132)*4)
__global__ void gate_kernel(const float* __restrict__ Wg, const float* __restrict__ bg,
                            const float* __restrict__ gam, const float* __restrict__ bet,
                            const float* __restrict__ X, float* __restrict__ out) {
    extern __shared__ float sm[];
    float* sW  = sm;                 // [256][128]
    float* sIn = sm + 32768;         // [256][36] : concat(feat,stru) transposed, rows<32
    float* sF  = sIn + 256*36;       // [32][132] fused values
    int t = threadIdx.x;
    int r0 = blockIdx.x * 32;

    for (int q = t; q < 8192; q += 256) ((float4*)sW)[q] = ((const float4*)Wg)[q];
    for (int q = t; q < 32*32; q += 256) {
        int row = q >> 5, ch = q & 31;
        float4 f = *(const float4*)(S_feat + (size_t)(r0 + row) * DIM + ch * 4);
        float4 s = *(const float4*)(S_stru + (size_t)(r0 + row) * DIM + ch * 4);
        sIn[(ch*4+0)*36 + row] = f.x;
        sIn[(ch*4+1)*36 + row] = f.y;
        sIn[(ch*4+2)*36 + row] = f.z;
        sIn[(ch*4+3)*36 + row] = f.w;
        sIn[(128 + ch*4+0)*36 + row] = s.x;
        sIn[(128 + ch*4+1)*36 + row] = s.y;
        sIn[(128 + ch*4+2)*36 + row] = s.z;
        sIn[(128 + ch*4+3)*36 + row] = s.w;
    }
    __syncthreads();

    int tr = t >> 5, tc = t & 31;   // rows tr*4+m (32), cols tc*4+n (128)
    float acc[4][4];
    #pragma unroll
    for (int m = 0; m < 4; m++)
        #pragma unroll
        for (int n = 0; n < 4; n++) acc[m][n] = 0.f;

    #pragma unroll 4
    for (int k = 0; k < 256; k++) {
        float4 a = *(const float4*)(sIn + k*36 + tr*4);
        float4 b = *(const float4*)(sW + k*128 + tc*4);
        float av[4] = {a.x, a.y, a.z, a.w};
        float bv[4] = {b.x, b.y, b.z, b.w};
        #pragma unroll
        for (int m = 0; m < 4; m++)
            #pragma unroll
            for (int n = 0; n < 4; n++) acc[m][n] += av[m] * bv[n];
    }

    #pragma unroll
    for (int m = 0; m < 4; m++) {
        int row = tr*4 + m;
        #pragma unroll
        for (int n = 0; n < 4; n++) {
            int col = tc*4 + n;
            float z = acc[m][n] + bg[col];
            float gate = 1.0f / (1.0f + expf(-z));
            float fv = sIn[col*36 + row];
            float sv = sIn[(128 + col)*36 + row];
            sF[row*132 + col] = gate * fv + (1.0f - gate) * sv;
        }
    }
    __syncthreads();

    int wid = t >> 5, lane = t & 31;
    for (int r = wid; r < 32; r += 8) {
        float4 v = *(const float4*)(sF + r*132 + lane*4);
        float s1 = v.x + v.y + v.z + v.w;
        #pragma unroll
        for (int o = 16; o > 0; o >>= 1) s1 += __shfl_xor_sync(0xffffffffu, s1, o);
        float mean = s1 * (1.0f / 128.0f);
        float d0 = v.x - mean, d1 = v.y - mean, d2 = v.z - mean, d3 = v.w - mean;
        float q = d0*d0 + d1*d1 + d2*d2 + d3*d3;
        #pragma unroll
        for (int o = 16; o > 0; o >>= 1) q += __shfl_xor_sync(0xffffffffu, q, o);
        float rstd = rsqrtf(q * (1.0f / 128.0f) + 1e-5f);
        int gr = r0 + r;
        float4 gg = *(const float4*)(gam + lane * 4);
        float4 be = *(const float4*)(bet + lane * 4);
        float4 xr = *(const float4*)(X + (size_t)gr * DIM + lane * 4);
        float4 o4 = make_float4(d0*rstd*gg.x + be.x + xr.x,
                                d1*rstd*gg.y + be.y + xr.y,
                                d2*rstd*gg.z + be.z + xr.z,
                                d3*rstd*gg.w + be.w + xr.w);
        *(float4*)(out + (size_t)gr * DIM + lane * 4) = o4;
    }
}

// ---------------- launch ----------------
extern "C" void kernel_launch(void* const* d_in, const int* in_sizes, int n_in,
                              void* d_out, int out_size) {
    const float* x       = (const float*)d_in[0];
    const int*   eidx    = (const int*)d_in[1];
    const float* W_feat  = (const float*)d_in[2];
    const float* b_feat  = (const float*)d_in[3];
    const float* W_stru  = (const float*)d_in[4];
    const float* b_stru  = (const float*)d_in[5];
    const float* W_gate  = (const float*)d_in[6];
    const float* b_gate  = (const float*)d_in[7];
    const float* gm_feat = (const float*)d_in[8];
    const float* be_feat = (const float*)d_in[9];
    const float* gm_stru = (const float*)d_in[10];
    const float* be_stru = (const float*)d_in[11];
    const float* gm_fus  = (const float*)d_in[12];
    const float* be_fus  = (const float*)d_in[13];
    float* out = (float*)d_out;

    const int* e_src = eidx;
    const int* e_dst = eidx + EDGES;

    cudaFuncSetAttribute(topk_kernel,   cudaFuncAttributeMaxDynamicSharedMemorySize, TOPK_SMEM);
    cudaFuncSetAttribute(gemm128_kernel,cudaFuncAttributeMaxDynamicSharedMemorySize, GEMM_SMEM);
    cudaFuncSetAttribute(gate_kernel,   cudaFuncAttributeMaxDynamicSharedMemorySize, GATE_SMEM);

    float *p_xn, *p_hf, *p_hs, *p_feat, *p_stru, *p_dinv_s, *p_dinv_f;
    int *p_cnt_s, *p_off_s, *p_cnt_f, *p_off_f, *p_csr_s, *p_csr_f;
    cudaGetSymbolAddress((void**)&p_xn, S_xn);
    cudaGetSymbolAddress((void**)&p_hf, S_hf);
    cudaGetSymbolAddress((void**)&p_hs, S_hs);
    cudaGetSymbolAddress((void**)&p_feat, S_feat);
    cudaGetSymbolAddress((void**)&p_stru, S_stru);
    cudaGetSymbolAddress((void**)&p_dinv_s, S_dinv_s);
    cudaGetSymbolAddress((void**)&p_dinv_f, S_dinv_f);
    cudaGetSymbolAddress((void**)&p_cnt_s, S_cnt_s);
    cudaGetSymbolAddress((void**)&p_off_s, S_off_s);
    cudaGetSymbolAddress((void**)&p_cnt_f, S_cnt_f);
    cudaGetSymbolAddress((void**)&p_off_f, S_off_f);
    cudaGetSymbolAddress((void**)&p_csr_s, S_csr_s);
    cudaGetSymbolAddress((void**)&p_csr_f, S_csr_f);
    int *p_cur_s, *p_cur_f;
    cudaGetSymbolAddress((void**)&p_cur_s, S_cur_s);
    cudaGetSymbolAddress((void**)&p_cur_f, S_cur_f);

    zero_counts_kernel<<<NN/256, 256>>>();
    count_stru_kernel<<<EDGES/256, 256>>>(e_dst);
    normalize_kernel<<<NN/8, 256>>>(x);
    gemm128_kernel<<<NN/64, 256, GEMM_SMEM>>>(x, W_feat, p_hf);
    gemm128_kernel<<<NN/64, 256, GEMM_SMEM>>>(x, W_stru, p_hs);
    topk_kernel<<<NGRAPH*16, 256, TOPK_SMEM>>>(nullptr);
    scan_kernel<<<1, 1024>>>(p_cnt_s, p_off_s, p_cur_s);
    scan_kernel<<<1, 1024>>>(p_cnt_f, p_off_f, p_cur_f);
    scatter_stru_kernel<<<EDGES/256, 256>>>(e_src, e_dst);
    scatter_feat_kernel<<<FEDGES/256, 256>>>();
    dinv_kernel<<<NN/256, 256>>>();
    agg_ln_kernel<<<NN/8, 256>>>(p_hf, p_csr_f, p_off_f, p_cnt_f, p_dinv_f,
                                 b_feat, gm_feat, be_feat, p_feat);
    agg_ln_kernel<<<NN/8, 256>>>(p_hs, p_csr_s, p_off_s, p_cnt_s, p_dinv_s,
                                 b_stru, gm_stru, be_stru, p_stru);
    gate_kernel<<<NN/32, 256, GATE_SMEM>>>(W_gate, b_gate, gm_fus, be_fus, x, out);
    (void)in_sizes; (void)n_in; (void)out_size;
}

// round 9
// speedup vs baseline: 1.1271x; 1.1271x over previous
#include <cuda_runtime.h>
#include <cuda_bf16.h>
#include <cstdint>
#include <math.h>
#include <float.h>

#define NN      65536
#define NGRAPH  64
#define GN      1024
#define DIM     128
#define EDGES   2097152
#define FK      4
#define FEDGES  (NN*FK)

// ---------------- scratch (no allocations allowed) ----------------
__device__ float         S_xn[(size_t)NN*DIM];    // fp32 normalized rows
__device__ __nv_bfloat16 S_xbf[(size_t)NN*DIM];   // bf16 of normalized rows
__device__ float S_hf[NN*DIM];
__device__ float S_hs[NN*DIM];
__device__ float S_feat[NN*DIM];
__device__ float S_stru[NN*DIM];
__device__ int   S_fdst[FEDGES];
__device__ int   S_cnt_s[NN], S_off_s[NN], S_cur_s[NN];
__device__ int   S_cnt_f[NN], S_off_f[NN], S_cur_f[NN];
__device__ float S_dinv_s[NN], S_dinv_f[NN];
__device__ int   S_csr_s[EDGES];
__device__ int   S_csr_f[FEDGES];

// ---------------- small helpers ----------------
__device__ __forceinline__ bool cand_better(float da, int ja, float db, int jb) {
    // "farther" = smaller dot; tie -> smaller index (top_k tie rule)
    return (da < db) || (da == db && ja < jb);
}

// ---------------- 0: zero degree counters ----------------
__global__ void zero_counts_kernel() {
    int i = blockIdx.x * blockDim.x + threadIdx.x;
    if (i < NN) { S_cnt_s[i] = 0; S_cnt_f[i] = 0; }
}

// ---------------- 1: structural in-degree ----------------
__global__ void count_stru_kernel(const int* __restrict__ dst) {
    int e = blockIdx.x * blockDim.x + threadIdx.x;
    if (e < EDGES) atomicAdd(&S_cnt_s[dst[e]], 1);
}

// ---------------- 2: normalize; store fp32 + bf16 copies ----------------
__global__ void split_kernel(const float* __restrict__ X) {
    int w = (blockIdx.x * blockDim.x + threadIdx.x) >> 5;
    int l = threadIdx.x & 31;
    if (w >= NN) return;
    float4 v = *(const float4*)(X + (size_t)w * DIM + l * 4);
    float ss = v.x*v.x + v.y*v.y + v.z*v.z + v.w*v.w;
    #pragma unroll
    for (int o = 16; o > 0; o >>= 1) ss += __shfl_xor_sync(0xffffffffu, ss, o);
    float inv = 1.0f / fmaxf(sqrtf(ss), 1e-8f);
    float xs[4] = {v.x*inv, v.y*inv, v.z*inv, v.w*inv};
    *(float4*)(S_xn + (size_t)w * DIM + l * 4) = make_float4(xs[0], xs[1], xs[2], xs[3]);
    __nv_bfloat16 hb[4];
    #pragma unroll
    for (int i = 0; i < 4; i++) hb[i] = __float2bfloat16(xs[i]);
    *(uint2*)(S_xbf + (size_t)w * DIM + l * 4) = *(uint2*)hb;
}

// ---------------- 3: mma.sync bf16 screening + fp32 rescore top-4 ----------------
// smem layout (bytes):
//   A  : 128 rows x 136 bf16 (stride 272B)   [0, 34816)
//   B  : same                                 [34816, 69632)
//   C  : 128 rows x 134 f32  (stride 536B)    [69632, 138240)   (reused as merge buf)
#define SA_STRIDE 136
#define SC_STRIDE 134
#define TOPK_SMEM_OFF_B 34816
#define TOPK_SMEM_OFF_C 69632
#define TOPK_SMEM_BYTES 138240

__device__ __forceinline__ void mma_bf16(float* c, uint32_t a0, uint32_t a1,
                                         uint32_t a2, uint32_t a3,
                                         uint32_t b0, uint32_t b1) {
    asm volatile(
        "mma.sync.aligned.m16n8k16.row.col.f32.bf16.bf16.f32 "
        "{%0,%1,%2,%3}, {%4,%5,%6,%7}, {%8,%9}, {%0,%1,%2,%3};"
        : "+f"(c[0]), "+f"(c[1]), "+f"(c[2]), "+f"(c[3])
        : "r"(a0), "r"(a1), "r"(a2), "r"(a3), "r"(b0), "r"(b1));
}

__global__ void __launch_bounds__(256, 1) topk_mma_kernel() {
    extern __shared__ char smc[];
    __nv_bfloat16* sA = (__nv_bfloat16*)smc;
    __nv_bfloat16* sB = (__nv_bfloat16*)(smc + TOPK_SMEM_OFF_B);
    float*         sC = (float*)(smc + TOPK_SMEM_OFF_C);

    int t = threadIdx.x;
    int g = blockIdx.x >> 3, it = blockIdx.x & 7;
    int warp = t >> 5, lane = t & 31;
    int gq = lane >> 2, qq = lane & 3;           // group / thread-in-group
    int warp_m = warp >> 1, warp_n = warp & 1;   // 4 x 2 warp grid
    int mb = warp_m * 32, nb = warp_n * 64;
    const int gbase = g * GN;

    // load A tile (rows it*128 .. +128)
    {
        const __nv_bfloat16* src = S_xbf + (size_t)(gbase + it * 128) * DIM;
        for (int v = t; v < 2048; v += 256) {
            int r = v >> 4, sg = v & 15;
            uint4 d = *(const uint4*)(src + (size_t)r * DIM + sg * 8);
            *(uint4*)((char*)sA + r * (SA_STRIDE * 2) + sg * 16) = d;
        }
    }

    // per-thread screening top-8 (thread t: row = t&127, cols half (t>>7))
    int selrow = t & 127, selhalf = t >> 7;
    float sv[8]; int si[8];
    #pragma unroll
    for (int r = 0; r < 8; r++) { sv[r] = FLT_MAX; si[r] = 0x7fffffff; }

    for (int jc = 0; jc < 8; jc++) {
        // load B chunk
        {
            const __nv_bfloat16* src = S_xbf + (size_t)(gbase + jc * 128) * DIM;
            for (int v = t; v < 2048; v += 256) {
                int r = v >> 4, sg = v & 15;
                uint4 d = *(const uint4*)(src + (size_t)r * DIM + sg * 8);
                *(uint4*)((char*)sB + r * (SA_STRIDE * 2) + sg * 16) = d;
            }
        }
        __syncthreads();

        float acc[2][8][4];
        #pragma unroll
        for (int mt = 0; mt < 2; mt++)
            #pragma unroll
            for (int nt = 0; nt < 8; nt++)
                #pragma unroll
                for (int r = 0; r < 4; r++) acc[mt][nt][r] = 0.f;

        #pragma unroll
        for (int ks = 0; ks < 8; ks++) {
            uint32_t bf[8][2];
            #pragma unroll
            for (int nt = 0; nt < 8; nt++) {
                const __nv_bfloat16* bp = sB + (nb + nt * 8 + gq) * SA_STRIDE + ks * 16 + qq * 2;
                bf[nt][0] = *(const uint32_t*)bp;
                bf[nt][1] = *(const uint32_t*)(bp + 8);
            }
            #pragma unroll
            for (int mt = 0; mt < 2; mt++) {
                const __nv_bfloat16* ap = sA + (mb + mt * 16 + gq) * SA_STRIDE + ks * 16 + qq * 2;
                uint32_t a0 = *(const uint32_t*)ap;
                uint32_t a1 = *(const uint32_t*)(ap + 8 * SA_STRIDE);
                uint32_t a2 = *(const uint32_t*)(ap + 8);
                uint32_t a3 = *(const uint32_t*)(ap + 8 * SA_STRIDE + 8);
                #pragma unroll
                for (int nt = 0; nt < 8; nt++)
                    mma_bf16(acc[mt][nt], a0, a1, a2, a3, bf[nt][0], bf[nt][1]);
            }
        }

        // store dots to sC
        #pragma unroll
        for (int mt = 0; mt < 2; mt++) {
            int row0 = mb + mt * 16 + gq;
            #pragma unroll
            for (int nt = 0; nt < 8; nt++) {
                int col = nb + nt * 8 + qq * 2;
                *(float2*)&sC[row0 * SC_STRIDE + col] =
                    make_float2(acc[mt][nt][0], acc[mt][nt][1]);
                *(float2*)&sC[(row0 + 8) * SC_STRIDE + col] =
                    make_float2(acc[mt][nt][2], acc[mt][nt][3]);
            }
        }
        __syncthreads();

        // screening scan: 64 dots per thread
        const float* crow = sC + selrow * SC_STRIDE + selhalf * 64;
        int jb = jc * 128 + selhalf * 64;
        #pragma unroll 4
        for (int c = 0; c < 64; c++) {
            float dv = crow[c];
            int jl = jb + c;
            if (cand_better(dv, jl, sv[7], si[7])) {
                sv[7] = dv; si[7] = jl;
                #pragma unroll
                for (int r = 7; r >= 1; r--) {
                    if (cand_better(sv[r], si[r], sv[r-1], si[r-1])) {
                        float td = sv[r]; sv[r] = sv[r-1]; sv[r-1] = td;
                        int   ti = si[r]; si[r] = si[r-1]; si[r-1] = ti;
                    }
                }
            }
        }
        __syncthreads();   // sC / sB reuse next chunk
    }

    // merge halves via smem (alias sC region)
    float* MV = sC;                 // [128][16]
    int*   MI = (int*)(sC + 2048);  // [128][16]
    #pragma unroll
    for (int r = 0; r < 8; r++) {
        MV[selrow * 16 + selhalf * 8 + r] = sv[r];
        MI[selrow * 16 + selhalf * 8 + r] = si[r];
    }
    __syncthreads();

    if (t < 128) {
        int row = t;
        float mv[8]; int mi[8];
        #pragma unroll
        for (int r = 0; r < 8; r++) { mv[r] = FLT_MAX; mi[r] = 0x7fffffff; }
        #pragma unroll
        for (int c = 0; c < 16; c++) {
            float dv = MV[row * 16 + c];
            int   jl = MI[row * 16 + c];
            if (cand_better(dv, jl, mv[7], mi[7])) {
                mv[7] = dv; mi[7] = jl;
                #pragma unroll
                for (int r = 7; r >= 1; r--) {
                    if (cand_better(mv[r], mi[r], mv[r-1], mi[r-1])) {
                        float td = mv[r]; mv[r] = mv[r-1]; mv[r-1] = td;
                        int   ti = mi[r]; mi[r] = mi[r-1]; mi[r-1] = ti;
                    }
                }
            }
        }

        // exact fp32 rescore of the 8 candidates; pick top-4
        int inode = gbase + it * 128 + row;
        const float* xi = S_xn + (size_t)inode * DIM;
        float t4d[4]; int t4i[4];
        #pragma unroll
        for (int r = 0; r < 4; r++) { t4d[r] = FLT_MAX; t4i[r] = 0x7fffffff; }
        #pragma unroll
        for (int c = 0; c < 8; c++) {
            int j = mi[c];
            const float* xj = S_xn + (size_t)(gbase + j) * DIM;
            float dot = 0.f;
            #pragma unroll 8
            for (int kk = 0; kk < 32; kk++) {
                float4 a = *(const float4*)(xi + kk * 4);
                float4 b = *(const float4*)(xj + kk * 4);
                dot += a.x*b.x + a.y*b.y + a.z*b.z + a.w*b.w;
            }
            if (cand_better(dot, j, t4d[3], t4i[3])) {
                t4d[3] = dot; t4i[3] = j;
                #pragma unroll
                for (int r = 3; r >= 1; r--) {
                    if (cand_better(t4d[r], t4i[r], t4d[r-1], t4i[r-1])) {
                        float td = t4d[r]; t4d[r] = t4d[r-1]; t4d[r-1] = td;
                        int   ti = t4i[r]; t4i[r] = t4i[r-1]; t4i[r-1] = ti;
                    }
                }
            }
        }
        #pragma unroll
        for (int r = 0; r < 4; r++) {
            int dg = gbase + t4i[r];
            S_fdst[inode * 4 + r] = dg;
            atomicAdd(&S_cnt_f[dg], 1);
        }
    }
}

// ---------------- 4: H = X @ W  (K = DIM = 128) ----------------
#define GEMM_SMEM ((16384 + 128*68)*4)
__global__ void gemm128_kernel(const float* __restrict__ X, const float* __restrict__ W,
                               float* __restrict__ H) {
    extern __shared__ float smf[];
    float* sW = smf;            // [128][128]
    float* sX = smf + 16384;    // [128][68] d-major
    int t = threadIdx.x;
    int r0 = blockIdx.x * 64;

    for (int q = t; q < 4096; q += 256) ((float4*)sW)[q] = ((const float4*)W)[q];
    for (int q = t; q < 2048; q += 256) {
        int row = q >> 5, ch = q & 31;
        float4 v = *(const float4*)(X + (size_t)(r0 + row) * DIM + ch * 4);
        sX[(ch*4+0)*68 + row] = v.x;
        sX[(ch*4+1)*68 + row] = v.y;
        sX[(ch*4+2)*68 + row] = v.z;
        sX[(ch*4+3)*68 + row] = v.w;
    }
    __syncthreads();

    int tr = t >> 4, tc = t & 15;   // rows tr*4+m, cols tc*8+n
    float acc[4][8];
    #pragma unroll
    for (int m = 0; m < 4; m++)
        #pragma unroll
        for (int n = 0; n < 8; n++) acc[m][n] = 0.f;

    #pragma unroll 4
    for (int k = 0; k < 128; k++) {
        float4 a  = *(const float4*)(sX + k*68 + tr*4);
        float4 b0 = *(const float4*)(sW + k*128 + tc*8);
        float4 b1 = *(const float4*)(sW + k*128 + tc*8 + 4);
        float av[4] = {a.x, a.y, a.z, a.w};
        float bv[8] = {b0.x, b0.y, b0.z, b0.w, b1.x, b1.y, b1.z, b1.w};
        #pragma unroll
        for (int m = 0; m < 4; m++)
            #pragma unroll
            for (int n = 0; n < 8; n++) acc[m][n] += av[m] * bv[n];
    }
    #pragma unroll
    for (int m = 0; m < 4; m++) {
        int row = r0 + tr*4 + m;
        #pragma unroll
        for (int n = 0; n < 8; n += 4) {
            float4 o4 = make_float4(acc[m][n], acc[m][n+1], acc[m][n+2], acc[m][n+3]);
            *(float4*)(H + (size_t)row * DIM + tc*8 + n) = o4;
        }
    }
}

// ---------------- 5: exclusive scan (one block, 1024 threads, n=65536) ----------------
__global__ void scan_kernel(const int* __restrict__ cnt, int* __restrict__ off,
                            int* __restrict__ cur) {
    __shared__ int wsum[32];
    int t = threadIdx.x;
    int base = t * 64;
    int s = 0;
    for (int i = 0; i < 64; i++) s += cnt[base + i];
    int lane = t & 31, wid = t >> 5;
    int v = s;
    #pragma unroll
    for (int o = 1; o < 32; o <<= 1) {
        int u = __shfl_up_sync(0xffffffffu, v, o);
        if (lane >= o) v += u;
    }
    if (lane == 31) wsum[wid] = v;
    __syncthreads();
    if (wid == 0) {
        int w = wsum[lane];
        #pragma unroll
        for (int o = 1; o < 32; o <<= 1) {
            int u = __shfl_up_sync(0xffffffffu, w, o);
            if (lane >= o) w += u;
        }
        wsum[lane] = w;
    }
    __syncthreads();
    int excl = v - s + (wid > 0 ? wsum[wid - 1] : 0);
    int run = excl;
    for (int i = 0; i < 64; i++) {
        off[base + i] = run;
        cur[base + i] = run;
        run += cnt[base + i];
    }
}

// ---------------- 6: scatter to CSR ----------------
__global__ void scatter_stru_kernel(const int* __restrict__ src, const int* __restrict__ dst) {
    int e = blockIdx.x * blockDim.x + threadIdx.x;
    if (e < EDGES) {
        int d = dst[e];
        int p = atomicAdd(&S_cur_s[d], 1);
        S_csr_s[p] = src[e];
    }
}
__global__ void scatter_feat_kernel() {
    int e = blockIdx.x * blockDim.x + threadIdx.x;
    if (e < FEDGES) {
        int d = S_fdst[e];
        int p = atomicAdd(&S_cur_f[d], 1);
        S_csr_f[p] = e >> 2;   // src node
    }
}

// ---------------- 7: dinv = rsqrt(indeg + 1) ----------------
__global__ void dinv_kernel() {
    int i = blockIdx.x * blockDim.x + threadIdx.x;
    if (i < NN) {
        S_dinv_s[i] = rsqrtf((float)(S_cnt_s[i] + 1));
        S_dinv_f[i] = rsqrtf((float)(S_cnt_f[i] + 1));
    }
}

// ---------------- 8: aggregate + bias + relu + LN (warp per node) ----------------
__global__ void agg_ln_kernel(const float* __restrict__ H, const int* __restrict__ csr,
                              const int* __restrict__ off, const int* __restrict__ cnt,
                              const float* __restrict__ dinv,
                              const float* __restrict__ bias, const float* __restrict__ gamma,
                              const float* __restrict__ beta, float* __restrict__ out) {
    int w = (blockIdx.x * blockDim.x + threadIdx.x) >> 5;
    int l = threadIdx.x & 31;
    if (w >= NN) return;
    float dv = dinv[w];
    float4 hv = *(const float4*)(H + (size_t)w * DIM + l * 4);
    float sw = dv * dv;
    float4 acc = make_float4(hv.x*sw, hv.y*sw, hv.z*sw, hv.w*sw);
    int base = off[w], n = cnt[w];
    int e = 0;
    for (; e + 1 < n; e += 2) {
        int s0 = csr[base + e], s1 = csr[base + e + 1];
        float w0 = dinv[s0] * dv, w1 = dinv[s1] * dv;
        float4 h0 = *(const float4*)(H + (size_t)s0 * DIM + l * 4);
        float4 h1 = *(const float4*)(H + (size_t)s1 * DIM + l * 4);
        acc.x += w0*h0.x + w1*h1.x;
        acc.y += w0*h0.y + w1*h1.y;
        acc.z += w0*h0.z + w1*h1.z;
        acc.w += w0*h0.w + w1*h1.w;
    }
    if (e < n) {
        int s0 = csr[base + e];
        float w0 = dinv[s0] * dv;
        float4 h0 = *(const float4*)(H + (size_t)s0 * DIM + l * 4);
        acc.x += w0*h0.x; acc.y += w0*h0.y; acc.z += w0*h0.z; acc.w += w0*h0.w;
    }
    float4 bb = *(const float4*)(bias + l * 4);
    float v0 = fmaxf(acc.x + bb.x, 0.f);
    float v1 = fmaxf(acc.y + bb.y, 0.f);
    float v2 = fmaxf(acc.z + bb.z, 0.f);
    float v3 = fmaxf(acc.w + bb.w, 0.f);
    float s1 = v0 + v1 + v2 + v3;
    #pragma unroll
    for (int o = 16; o > 0; o >>= 1) s1 += __shfl_xor_sync(0xffffffffu, s1, o);
    float mean = s1 * (1.0f / 128.0f);
    float d0 = v0 - mean, d1 = v1 - mean, d2 = v2 - mean, d3 = v3 - mean;
    float q = d0*d0 + d1*d1 + d2*d2 + d3*d3;
    #pragma unroll
    for (int o = 16; o > 0; o >>= 1) q += __shfl_xor_sync(0xffffffffu, q, o);
    float rstd = rsqrtf(q * (1.0f / 128.0f) + 1e-5f);
    float4 gg = *(const float4*)(gamma + l * 4);
    float4 be = *(const float4*)(beta + l * 4);
    float4 o4 = make_float4(d0*rstd*gg.x + be.x, d1*rstd*gg.y + be.y,
                            d2*rstd*gg.z + be.z, d3*rstd*gg.w + be.w);
    *(float4*)(out + (size_t)w * DIM + l * 4) = o4;
}

// ---------------- 9: gate GEMM + sigmoid + fuse + LN + residual ----------------
#define GATE_SMEM ((32768 + 256*36 + 32*132)*4)
__global__ void gate_kernel(const float* __restrict__ Wg, const float* __restrict__ bg,
                            const float* __restrict__ gam, const float* __restrict__ bet,
                            const float* __restrict__ X, float* __restrict__ out) {
    extern __shared__ float smf[];
    float* sW  = smf;                // [256][128]
    float* sIn = smf + 32768;        // [256][36] : concat(feat,stru) transposed, rows<32
    float* sF  = sIn + 256*36;       // [32][132] fused values
    int t = threadIdx.x;
    int r0 = blockIdx.x * 32;

    for (int q = t; q < 8192; q += 256) ((float4*)sW)[q] = ((const float4*)Wg)[q];
    for (int q = t; q < 32*32; q += 256) {
        int row = q >> 5, ch = q & 31;
        float4 f = *(const float4*)(S_feat + (size_t)(r0 + row) * DIM + ch * 4);
        float4 s = *(const float4*)(S_stru + (size_t)(r0 + row) * DIM + ch * 4);
        sIn[(ch*4+0)*36 + row] = f.x;
        sIn[(ch*4+1)*36 + row] = f.y;
        sIn[(ch*4+2)*36 + row] = f.z;
        sIn[(ch*4+3)*36 + row] = f.w;
        sIn[(128 + ch*4+0)*36 + row] = s.x;
        sIn[(128 + ch*4+1)*36 + row] = s.y;
        sIn[(128 + ch*4+2)*36 + row] = s.z;
        sIn[(128 + ch*4+3)*36 + row] = s.w;
    }
    __syncthreads();

    int tr = t >> 5, tc = t & 31;   // rows tr*4+m (32), cols tc*4+n (128)
    float acc[4][4];
    #pragma unroll
    for (int m = 0; m < 4; m++)
        #pragma unroll
        for (int n = 0; n < 4; n++) acc[m][n] = 0.f;

    #pragma unroll 4
    for (int k = 0; k < 256; k++) {
        float4 a = *(const float4*)(sIn + k*36 + tr*4);
        float4 b = *(const float4*)(sW + k*128 + tc*4);
        float av[4] = {a.x, a.y, a.z, a.w};
        float bv[4] = {b.x, b.y, b.z, b.w};
        #pragma unroll
        for (int m = 0; m < 4; m++)
            #pragma unroll
            for (int n = 0; n < 4; n++) acc[m][n] += av[m] * bv[n];
    }

    #pragma unroll
    for (int m = 0; m < 4; m++) {
        int row = tr*4 + m;
        #pragma unroll
        for (int n = 0; n < 4; n++) {
            int col = tc*4 + n;
            float z = acc[m][n] + bg[col];
            float gate = 1.0f / (1.0f + expf(-z));
            float fv = sIn[col*36 + row];
            float sv = sIn[(128 + col)*36 + row];
            sF[row*132 + col] = gate * fv + (1.0f - gate) * sv;
        }
    }
    __syncthreads();

    int wid = t >> 5, lane = t & 31;
    for (int r = wid; r < 32; r += 8) {
        float4 v = *(const float4*)(sF + r*132 + lane*4);
        float s1 = v.x + v.y + v.z + v.w;
        #pragma unroll
        for (int o = 16; o > 0; o >>= 1) s1 += __shfl_xor_sync(0xffffffffu, s1, o);
        float mean = s1 * (1.0f / 128.0f);
        float d0 = v.x - mean, d1 = v.y - mean, d2 = v.z - mean, d3 = v.w - mean;
        float q = d0*d0 + d1*d1 + d2*d2 + d3*d3;
        #pragma unroll
        for (int o = 16; o > 0; o >>= 1) q += __shfl_xor_sync(0xffffffffu, q, o);
        float rstd = rsqrtf(q * (1.0f / 128.0f) + 1e-5f);
        int gr = r0 + r;
        float4 gg = *(const float4*)(gam + lane * 4);
        float4 be = *(const float4*)(bet + lane * 4);
        float4 xr = *(const float4*)(X + (size_t)gr * DIM + lane * 4);
        float4 o4 = make_float4(d0*rstd*gg.x + be.x + xr.x,
                                d1*rstd*gg.y + be.y + xr.y,
                                d2*rstd*gg.z + be.z + xr.z,
                                d3*rstd*gg.w + be.w + xr.w);
        *(float4*)(out + (size_t)gr * DIM + lane * 4) = o4;
    }
}

// ---------------- launch ----------------
extern "C" void kernel_launch(void* const* d_in, const int* in_sizes, int n_in,
                              void* d_out, int out_size) {
    const float* x       = (const float*)d_in[0];
    const int*   eidx    = (const int*)d_in[1];
    const float* W_feat  = (const float*)d_in[2];
    const float* b_feat  = (const float*)d_in[3];
    const float* W_stru  = (const float*)d_in[4];
    const float* b_stru  = (const float*)d_in[5];
    const float* W_gate  = (const float*)d_in[6];
    const float* b_gate  = (const float*)d_in[7];
    const float* gm_feat = (const float*)d_in[8];
    const float* be_feat = (const float*)d_in[9];
    const float* gm_stru = (const float*)d_in[10];
    const float* be_stru = (const float*)d_in[11];
    const float* gm_fus  = (const float*)d_in[12];
    const float* be_fus  = (const float*)d_in[13];
    float* out = (float*)d_out;

    const int* e_src = eidx;
    const int* e_dst = eidx + EDGES;

    cudaFuncSetAttribute(topk_mma_kernel, cudaFuncAttributeMaxDynamicSharedMemorySize, TOPK_SMEM_BYTES);
    cudaFuncSetAttribute(gemm128_kernel,  cudaFuncAttributeMaxDynamicSharedMemorySize, GEMM_SMEM);
    cudaFuncSetAttribute(gate_kernel,     cudaFuncAttributeMaxDynamicSharedMemorySize, GATE_SMEM);

    float *p_hf, *p_hs, *p_feat, *p_stru, *p_dinv_s, *p_dinv_f;
    int *p_cnt_s, *p_off_s, *p_cnt_f, *p_off_f, *p_csr_s, *p_csr_f, *p_cur_s, *p_cur_f;
    cudaGetSymbolAddress((void**)&p_hf, S_hf);
    cudaGetSymbolAddress((void**)&p_hs, S_hs);
    cudaGetSymbolAddress((void**)&p_feat, S_feat);
    cudaGetSymbolAddress((void**)&p_stru, S_stru);
    cudaGetSymbolAddress((void**)&p_dinv_s, S_dinv_s);
    cudaGetSymbolAddress((void**)&p_dinv_f, S_dinv_f);
    cudaGetSymbolAddress((void**)&p_cnt_s, S_cnt_s);
    cudaGetSymbolAddress((void**)&p_off_s, S_off_s);
    cudaGetSymbolAddress((void**)&p_cnt_f, S_cnt_f);
    cudaGetSymbolAddress((void**)&p_off_f, S_off_f);
    cudaGetSymbolAddress((void**)&p_csr_s, S_csr_s);
    cudaGetSymbolAddress((void**)&p_csr_f, S_csr_f);
    cudaGetSymbolAddress((void**)&p_cur_s, S_cur_s);
    cudaGetSymbolAddress((void**)&p_cur_f, S_cur_f);

    zero_counts_kernel<<<NN/256, 256>>>();
    count_stru_kernel<<<EDGES/256, 256>>>(e_dst);
    split_kernel<<<NN/8, 256>>>(x);
    gemm128_kernel<<<NN/64, 256, GEMM_SMEM>>>(x, W_feat, p_hf);
    gemm128_kernel<<<NN/64, 256, GEMM_SMEM>>>(x, W_stru, p_hs);
    topk_mma_kernel<<<NGRAPH*8, 256, TOPK_SMEM_BYTES>>>();
    scan_kernel<<<1, 1024>>>(p_cnt_s, p_off_s, p_cur_s);
    scan_kernel<<<1, 1024>>>(p_cnt_f, p_off_f, p_cur_f);
    scatter_stru_kernel<<<EDGES/256, 256>>>(e_src, e_dst);
    scatter_feat_kernel<<<FEDGES/256, 256>>>();
    dinv_kernel<<<NN/256, 256>>>();
    agg_ln_kernel<<<NN/8, 256>>>(p_hf, p_csr_f, p_off_f, p_cnt_f, p_dinv_f,
                                 b_feat, gm_feat, be_feat, p_feat);
    agg_ln_kernel<<<NN/8, 256>>>(p_hs, p_csr_s, p_off_s, p_cnt_s, p_dinv_s,
                                 b_stru, gm_stru, be_stru, p_stru);
    gate_kernel<<<NN/32, 256, GATE_SMEM>>>(W_gate, b_gate, gm_fus, be_fus, x, out);
    (void)in_sizes; (void)n_in; (void)out_size;
}

// round 12
// speedup vs baseline: 1.4746x; 1.3083x over previous
#include <cuda_runtime.h>
#include <cuda_bf16.h>
#include <cstdint>
#include <math.h>
#include <float.h>

#define NN      65536
#define NGRAPH  64
#define GN      1024
#define DIM     128
#define EDGES   2097152
#define FK      4
#define FEDGES  (NN*FK)

// ---------------- scratch (no allocations allowed) ----------------
__device__ float         S_xn[(size_t)NN*DIM];    // fp32 normalized rows
__device__ __nv_bfloat16 S_xbf[(size_t)NN*DIM];   // bf16 of normalized rows
__device__ __nv_bfloat16 S_xh[(size_t)NN*DIM];    // bf16 hi of raw x
__device__ __nv_bfloat16 S_xl[(size_t)NN*DIM];    // bf16 lo of raw x
__device__ float S_hf[NN*DIM];
__device__ float S_hs[NN*DIM];
__device__ float S_feat[NN*DIM];
__device__ float S_stru[NN*DIM];
__device__ __nv_bfloat16 S_feat_h[(size_t)NN*DIM], S_feat_l[(size_t)NN*DIM];
__device__ __nv_bfloat16 S_stru_h[(size_t)NN*DIM], S_stru_l[(size_t)NN*DIM];
__device__ int   S_fdst[FEDGES];
__device__ int   S_cnt_s[NN], S_off_s[NN], S_cur_s[NN];
__device__ int   S_cnt_f[NN], S_off_f[NN], S_cur_f[NN];
__device__ float S_dinv_s[NN], S_dinv_f[NN];
__device__ int   S_csr_s[EDGES];
__device__ int   S_csr_f[FEDGES];

// ---------------- small helpers ----------------
__device__ __forceinline__ bool cand_better(float da, int ja, float db, int jb) {
    return (da < db) || (da == db && ja < jb);
}

// ---------------- 0: zero degree counters ----------------
__global__ void zero_counts_kernel() {
    int i = blockIdx.x * blockDim.x + threadIdx.x;
    if (i < NN) { S_cnt_s[i] = 0; S_cnt_f[i] = 0; }
}

// ---------------- 1: structural in-degree ----------------
__global__ void count_stru_kernel(const int* __restrict__ dst) {
    int e = blockIdx.x * blockDim.x + threadIdx.x;
    if (e < EDGES) atomicAdd(&S_cnt_s[dst[e]], 1);
}

// ---------------- 2: normalize (fp32+bf16) + raw-x bf16 hi/lo split ----------------
__global__ void split_kernel(const float* __restrict__ X) {
    int w = (blockIdx.x * blockDim.x + threadIdx.x) >> 5;
    int l = threadIdx.x & 31;
    if (w >= NN) return;
    float4 v = *(const float4*)(X + (size_t)w * DIM + l * 4);
    float raw[4] = {v.x, v.y, v.z, v.w};
    float ss = v.x*v.x + v.y*v.y + v.z*v.z + v.w*v.w;
    #pragma unroll
    for (int o = 16; o > 0; o >>= 1) ss += __shfl_xor_sync(0xffffffffu, ss, o);
    float inv = 1.0f / fmaxf(sqrtf(ss), 1e-8f);
    float xs[4] = {v.x*inv, v.y*inv, v.z*inv, v.w*inv};
    *(float4*)(S_xn + (size_t)w * DIM + l * 4) = make_float4(xs[0], xs[1], xs[2], xs[3]);
    __nv_bfloat16 nb[4], rh[4], rl[4];
    #pragma unroll
    for (int i = 0; i < 4; i++) {
        nb[i] = __float2bfloat16(xs[i]);
        rh[i] = __float2bfloat16(raw[i]);
        rl[i] = __float2bfloat16(raw[i] - __bfloat162float(rh[i]));
    }
    *(uint2*)(S_xbf + (size_t)w * DIM + l * 4) = *(uint2*)nb;
    *(uint2*)(S_xh  + (size_t)w * DIM + l * 4) = *(uint2*)rh;
    *(uint2*)(S_xl  + (size_t)w * DIM + l * 4) = *(uint2*)rl;
}

// ---------------- shared mma.sync machinery ----------------
#define SA_STRIDE 136
#define SC_STRIDE 134

__device__ __forceinline__ void mma_bf16(float* c, uint32_t a0, uint32_t a1,
                                         uint32_t a2, uint32_t a3,
                                         uint32_t b0, uint32_t b1) {
    asm volatile(
        "mma.sync.aligned.m16n8k16.row.col.f32.bf16.bf16.f32 "
        "{%0,%1,%2,%3}, {%4,%5,%6,%7}, {%8,%9}, {%0,%1,%2,%3};"
        : "+f"(c[0]), "+f"(c[1]), "+f"(c[2]), "+f"(c[3])
        : "r"(a0), "r"(a1), "r"(a2), "r"(a3), "r"(b0), "r"(b1));
}

// one full K=128 pass: acc += A(128x128, rows mb..) * B(128x128, rows nb..)^T
__device__ __forceinline__ void mma_pass(const __nv_bfloat16* sA, const __nv_bfloat16* sB,
                                         float acc[2][8][4], int mb, int nb, int gq, int qq) {
    #pragma unroll
    for (int ks = 0; ks < 8; ks++) {
        uint32_t bf[8][2];
        #pragma unroll
        for (int nt = 0; nt < 8; nt++) {
            const __nv_bfloat16* bp = sB + (nb + nt * 8 + gq) * SA_STRIDE + ks * 16 + qq * 2;
            bf[nt][0] = *(const uint32_t*)bp;
            bf[nt][1] = *(const uint32_t*)(bp + 8);
        }
        #pragma unroll
        for (int mt = 0; mt < 2; mt++) {
            const __nv_bfloat16* ap = sA + (mb + mt * 16 + gq) * SA_STRIDE + ks * 16 + qq * 2;
            uint32_t a0 = *(const uint32_t*)ap;
            uint32_t a1 = *(const uint32_t*)(ap + 8 * SA_STRIDE);
            uint32_t a2 = *(const uint32_t*)(ap + 8);
            uint32_t a3 = *(const uint32_t*)(ap + 8 * SA_STRIDE + 8);
            #pragma unroll
            for (int nt = 0; nt < 8; nt++)
                mma_bf16(acc[mt][nt], a0, a1, a2, a3, bf[nt][0], bf[nt][1]);
        }
    }
}

// load 128x128 bf16 tile (row stride 128) into smem (row stride SA_STRIDE)
__device__ __forceinline__ void load_tile_bf16(__nv_bfloat16* dst,
                                               const __nv_bfloat16* src, int t) {
    for (int v = t; v < 2048; v += 256) {
        int r = v >> 4, sg = v & 15;
        uint4 d = *(const uint4*)(src + (size_t)r * 128 + sg * 8);
        *(uint4*)((char*)dst + r * (SA_STRIDE * 2) + sg * 16) = d;
    }
}

// load fp32 W[k][n] (128x128) transposed+split into sWh/sWl[n][k]
__device__ __forceinline__ void load_w_split(__nv_bfloat16* wh, __nv_bfloat16* wl,
                                             const float* __restrict__ W, int t) {
    for (int idx = t; idx < 16384; idx += 256) {
        int k = idx >> 7, n = idx & 127;
        float v = W[idx];
        __nv_bfloat16 h = __float2bfloat16(v);
        __nv_bfloat16 l = __float2bfloat16(v - __bfloat162float(h));
        wh[n * SA_STRIDE + k] = h;
        wl[n * SA_STRIDE + k] = l;
    }
}

// ---------------- 3: xgemm — H = X @ W for both weights, bf16 3-term split ----------------
#define XGEMM_SMEM (4*34816)
__global__ void __launch_bounds__(256, 1) xgemm_kernel(const float* __restrict__ Wf,
                                                       const float* __restrict__ Ws) {
    extern __shared__ char smc[];
    __nv_bfloat16* sAh = (__nv_bfloat16*)smc;
    __nv_bfloat16* sAl = (__nv_bfloat16*)(smc + 34816);
    __nv_bfloat16* sWh = (__nv_bfloat16*)(smc + 69632);
    __nv_bfloat16* sWl = (__nv_bfloat16*)(smc + 104448);

    int t = threadIdx.x;
    int warp = t >> 5, lane = t & 31;
    int gq = lane >> 2, qq = lane & 3;
    int mb = (warp >> 1) * 32, nb = (warp & 1) * 64;
    int r0 = blockIdx.x * 128;

    load_tile_bf16(sAh, S_xh + (size_t)r0 * 128, t);
    load_tile_bf16(sAl, S_xl + (size_t)r0 * 128, t);

    #pragma unroll
    for (int wsel = 0; wsel < 2; wsel++) {
        load_w_split(sWh, sWl, wsel ? Ws : Wf, t);
        __syncthreads();

        float acc[2][8][4];
        #pragma unroll
        for (int mt = 0; mt < 2; mt++)
            #pragma unroll
            for (int nt = 0; nt < 8; nt++)
                #pragma unroll
                for (int r = 0; r < 4; r++) acc[mt][nt][r] = 0.f;

        mma_pass(sAh, sWh, acc, mb, nb, gq, qq);
        mma_pass(sAh, sWl, acc, mb, nb, gq, qq);
        mma_pass(sAl, sWh, acc, mb, nb, gq, qq);

        float* H = wsel ? S_hs : S_hf;
        #pragma unroll
        for (int mt = 0; mt < 2; mt++) {
            int row0 = r0 + mb + mt * 16 + gq;
            #pragma unroll
            for (int nt = 0; nt < 8; nt++) {
                int col = nb + nt * 8 + qq * 2;
                *(float2*)(H + (size_t)row0 * DIM + col) =
                    make_float2(acc[mt][nt][0], acc[mt][nt][1]);
                *(float2*)(H + (size_t)(row0 + 8) * DIM + col) =
                    make_float2(acc[mt][nt][2], acc[mt][nt][3]);
            }
        }
        __syncthreads();   // all warps done with sW before next weight overwrites it
    }
}

// ---------------- 4: mma.sync bf16 screening + fp32 rescore top-4 ----------------
#define TOPK_SMEM_OFF_B 34816
#define TOPK_SMEM_OFF_C 69632
#define TOPK_SMEM_BYTES 138240

__global__ void __launch_bounds__(256, 1) topk_mma_kernel() {
    extern __shared__ char smc[];
    __nv_bfloat16* sA = (__nv_bfloat16*)smc;
    __nv_bfloat16* sB = (__nv_bfloat16*)(smc + TOPK_SMEM_OFF_B);
    float*         sC = (float*)(smc + TOPK_SMEM_OFF_C);

    int t = threadIdx.x;
    int g = blockIdx.x >> 3, it = blockIdx.x & 7;
    int warp = t >> 5, lane = t & 31;
    int gq = lane >> 2, qq = lane & 3;
    int mb = (warp >> 1) * 32, nb = (warp & 1) * 64;
    const int gbase = g * GN;

    load_tile_bf16(sA, S_xbf + (size_t)(gbase + it * 128) * DIM, t);

    int selrow = t & 127, selhalf = t >> 7;
    float sv[8]; int si[8];
    #pragma unroll
    for (int r = 0; r < 8; r++) { sv[r] = FLT_MAX; si[r] = 0x7fffffff; }

    for (int jc = 0; jc < 8; jc++) {
        load_tile_bf16(sB, S_xbf + (size_t)(gbase + jc * 128) * DIM, t);
        __syncthreads();

        float acc[2][8][4];
        #pragma unroll
        for (int mt = 0; mt < 2; mt++)
            #pragma unroll
            for (int nt = 0; nt < 8; nt++)
                #pragma unroll
                for (int r = 0; r < 4; r++) acc[mt][nt][r] = 0.f;

        mma_pass(sA, sB, acc, mb, nb, gq, qq);

        #pragma unroll
        for (int mt = 0; mt < 2; mt++) {
            int row0 = mb + mt * 16 + gq;
            #pragma unroll
            for (int nt = 0; nt < 8; nt++) {
                int col = nb + nt * 8 + qq * 2;
                *(float2*)&sC[row0 * SC_STRIDE + col] =
                    make_float2(acc[mt][nt][0], acc[mt][nt][1]);
                *(float2*)&sC[(row0 + 8) * SC_STRIDE + col] =
                    make_float2(acc[mt][nt][2], acc[mt][nt][3]);
            }
        }
        __syncthreads();

        const float* crow = sC + selrow * SC_STRIDE + selhalf * 64;
        int jb = jc * 128 + selhalf * 64;
        #pragma unroll 4
        for (int c = 0; c < 64; c++) {
            float dv = crow[c];
            int jl = jb + c;
            if (cand_better(dv, jl, sv[7], si[7])) {
                sv[7] = dv; si[7] = jl;
                #pragma unroll
                for (int r = 7; r >= 1; r--) {
                    if (cand_better(sv[r], si[r], sv[r-1], si[r-1])) {
                        float td = sv[r]; sv[r] = sv[r-1]; sv[r-1] = td;
                        int   ti = si[r]; si[r] = si[r-1]; si[r-1] = ti;
                    }
                }
            }
        }
        __syncthreads();
    }

    float* MV = sC;
    int*   MI = (int*)(sC + 2048);
    #pragma unroll
    for (int r = 0; r < 8; r++) {
        MV[selrow * 16 + selhalf * 8 + r] = sv[r];
        MI[selrow * 16 + selhalf * 8 + r] = si[r];
    }
    __syncthreads();

    if (t < 128) {
        int row = t;
        float mv[8]; int mi[8];
        #pragma unroll
        for (int r = 0; r < 8; r++) { mv[r] = FLT_MAX; mi[r] = 0x7fffffff; }
        #pragma unroll
        for (int c = 0; c < 16; c++) {
            float dv = MV[row * 16 + c];
            int   jl = MI[row * 16 + c];
            if (cand_better(dv, jl, mv[7], mi[7])) {
                mv[7] = dv; mi[7] = jl;
                #pragma unroll
                for (int r = 7; r >= 1; r--) {
                    if (cand_better(mv[r], mi[r], mv[r-1], mi[r-1])) {
                        float td = mv[r]; mv[r] = mv[r-1]; mv[r-1] = td;
                        int   ti = mi[r]; mi[r] = mi[r-1]; mi[r-1] = ti;
                    }
                }
            }
        }
        int inode = gbase + it * 128 + row;
        const float* xi = S_xn + (size_t)inode * DIM;
        float t4d[4]; int t4i[4];
        #pragma unroll
        for (int r = 0; r < 4; r++) { t4d[r] = FLT_MAX; t4i[r] = 0x7fffffff; }
        #pragma unroll
        for (int c = 0; c < 8; c++) {
            int j = mi[c];
            const float* xj = S_xn + (size_t)(gbase + j) * DIM;
            float dot = 0.f;
            #pragma unroll 8
            for (int kk = 0; kk < 32; kk++) {
                float4 a = *(const float4*)(xi + kk * 4);
                float4 b = *(const float4*)(xj + kk * 4);
                dot += a.x*b.x + a.y*b.y + a.z*b.z + a.w*b.w;
            }
            if (cand_better(dot, j, t4d[3], t4i[3])) {
                t4d[3] = dot; t4i[3] = j;
                #pragma unroll
                for (int r = 3; r >= 1; r--) {
                    if (cand_better(t4d[r], t4i[r], t4d[r-1], t4i[r-1])) {
                        float td = t4d[r]; t4d[r] = t4d[r-1]; t4d[r-1] = td;
                        int   ti = t4i[r]; t4i[r] = t4i[r-1]; t4i[r-1] = ti;
                    }
                }
            }
        }
        #pragma unroll
        for (int r = 0; r < 4; r++) {
            int dg = gbase + t4i[r];
            S_fdst[inode * 4 + r] = dg;
            atomicAdd(&S_cnt_f[dg], 1);
        }
    }
}

// ---------------- 5: exclusive scan (one block, 1024 threads, two-pass) ----------------
__global__ void __launch_bounds__(1024, 1) scan_kernel(const int* __restrict__ cnt,
                                                       int* __restrict__ off,
                                                       int* __restrict__ cur) {
    __shared__ int wsum[32];
    int t = threadIdx.x;
    const int4* c4 = (const int4*)(cnt + t * 64);
    // pass 1: per-thread sum (registers reused, not retained)
    int s = 0;
    #pragma unroll
    for (int i = 0; i < 16; i++) {
        int4 v = c4[i];
        s += v.x + v.y + v.z + v.w;
    }
    int lane = t & 31, wid = t >> 5;
    int v = s;
    #pragma unroll
    for (int o = 1; o < 32; o <<= 1) {
        int u = __shfl_up_sync(0xffffffffu, v, o);
        if (lane >= o) v += u;
    }
    if (lane == 31) wsum[wid] = v;
    __syncthreads();
    if (wid == 0) {
        int w = wsum[lane];
        #pragma unroll
        for (int o = 1; o < 32; o <<= 1) {
            int u = __shfl_up_sync(0xffffffffu, w, o);
            if (lane >= o) w += u;
        }
        wsum[lane] = w;
    }
    __syncthreads();
    int run = v - s + (wid > 0 ? wsum[wid - 1] : 0);
    // pass 2: re-read (L2-hot) and emit offsets
    int4* o4 = (int4*)(off + t * 64);
    int4* u4 = (int4*)(cur + t * 64);
    #pragma unroll
    for (int i = 0; i < 16; i++) {
        int4 cv = c4[i];
        int4 ov;
        ov.x = run; run += cv.x;
        ov.y = run; run += cv.y;
        ov.z = run; run += cv.z;
        ov.w = run; run += cv.w;
        o4[i] = ov; u4[i] = ov;
    }
}

// ---------------- 6: scatter to CSR ----------------
__global__ void scatter_stru_kernel(const int* __restrict__ src, const int* __restrict__ dst) {
    int e = blockIdx.x * blockDim.x + threadIdx.x;
    if (e < EDGES) {
        int d = dst[e];
        int p = atomicAdd(&S_cur_s[d], 1);
        S_csr_s[p] = src[e];
    }
}
__global__ void scatter_feat_kernel() {
    int e = blockIdx.x * blockDim.x + threadIdx.x;
    if (e < FEDGES) {
        int d = S_fdst[e];
        int p = atomicAdd(&S_cur_f[d], 1);
        S_csr_f[p] = e >> 2;
    }
}

// ---------------- 7: dinv = rsqrt(indeg + 1) ----------------
__global__ void dinv_kernel() {
    int i = blockIdx.x * blockDim.x + threadIdx.x;
    if (i < NN) {
        S_dinv_s[i] = rsqrtf((float)(S_cnt_s[i] + 1));
        S_dinv_f[i] = rsqrtf((float)(S_cnt_f[i] + 1));
    }
}

// ---------------- 8: aggregate + bias + relu + LN (+ bf16 split out) ----------------
__global__ void agg_ln_kernel(const float* __restrict__ H, const int* __restrict__ csr,
                              const int* __restrict__ off, const int* __restrict__ cnt,
                              const float* __restrict__ dinv,
                              const float* __restrict__ bias, const float* __restrict__ gamma,
                              const float* __restrict__ beta, float* __restrict__ out,
                              __nv_bfloat16* __restrict__ outh,
                              __nv_bfloat16* __restrict__ outl) {
    int w = (blockIdx.x * blockDim.x + threadIdx.x) >> 5;
    int l = threadIdx.x & 31;
    if (w >= NN) return;
    float dv = dinv[w];
    float4 hv = *(const float4*)(H + (size_t)w * DIM + l * 4);
    float sw = dv * dv;
    float4 acc = make_float4(hv.x*sw, hv.y*sw, hv.z*sw, hv.w*sw);
    int base = off[w], n = cnt[w];
    int e = 0;
    for (; e + 3 < n; e += 4) {
        int s0 = csr[base + e],     s1 = csr[base + e + 1];
        int s2 = csr[base + e + 2], s3 = csr[base + e + 3];
        float w0 = dinv[s0] * dv, w1 = dinv[s1] * dv;
        float w2 = dinv[s2] * dv, w3 = dinv[s3] * dv;
        float4 h0 = *(const float4*)(H + (size_t)s0 * DIM + l * 4);
        float4 h1 = *(const float4*)(H + (size_t)s1 * DIM + l * 4);
        float4 h2 = *(const float4*)(H + (size_t)s2 * DIM + l * 4);
        float4 h3 = *(const float4*)(H + (size_t)s3 * DIM + l * 4);
        acc.x += w0*h0.x + w1*h1.x + w2*h2.x + w3*h3.x;
        acc.y += w0*h0.y + w1*h1.y + w2*h2.y + w3*h3.y;
        acc.z += w0*h0.z + w1*h1.z + w2*h2.z + w3*h3.z;
        acc.w += w0*h0.w + w1*h1.w + w2*h2.w + w3*h3.w;
    }
    for (; e < n; e++) {
        int s0 = csr[base + e];
        float w0 = dinv[s0] * dv;
        float4 h0 = *(const float4*)(H + (size_t)s0 * DIM + l * 4);
        acc.x += w0*h0.x; acc.y += w0*h0.y; acc.z += w0*h0.z; acc.w += w0*h0.w;
    }
    float4 bb = *(const float4*)(bias + l * 4);
    float v0 = fmaxf(acc.x + bb.x, 0.f);
    float v1 = fmaxf(acc.y + bb.y, 0.f);
    float v2 = fmaxf(acc.z + bb.z, 0.f);
    float v3 = fmaxf(acc.w + bb.w, 0.f);
    float s1 = v0 + v1 + v2 + v3;
    #pragma unroll
    for (int o = 16; o > 0; o >>= 1) s1 += __shfl_xor_sync(0xffffffffu, s1, o);
    float mean = s1 * (1.0f / 128.0f);
    float d0 = v0 - mean, d1 = v1 - mean, d2 = v2 - mean, d3 = v3 - mean;
    float q = d0*d0 + d1*d1 + d2*d2 + d3*d3;
    #pragma unroll
    for (int o = 16; o > 0; o >>= 1) q += __shfl_xor_sync(0xffffffffu, q, o);
    float rstd = rsqrtf(q * (1.0f / 128.0f) + 1e-5f);
    float4 gg = *(const float4*)(gamma + l * 4);
    float4 be = *(const float4*)(beta + l * 4);
    float4 o4 = make_float4(d0*rstd*gg.x + be.x, d1*rstd*gg.y + be.y,
                            d2*rstd*gg.z + be.z, d3*rstd*gg.w + be.w);
    *(float4*)(out + (size_t)w * DIM + l * 4) = o4;
    float ov[4] = {o4.x, o4.y, o4.z, o4.w};
    __nv_bfloat16 hh[4], ll[4];
    #pragma unroll
    for (int i = 0; i < 4; i++) {
        hh[i] = __float2bfloat16(ov[i]);
        ll[i] = __float2bfloat16(ov[i] - __bfloat162float(hh[i]));
    }
    *(uint2*)(outh + (size_t)w * DIM + l * 4) = *(uint2*)hh;
    *(uint2*)(outl + (size_t)w * DIM + l * 4) = *(uint2*)ll;
}

// ---------------- 9: gate GEMM (bf16 split mma) + sigmoid + fuse + LN + residual ----------------
#define GATE2_SMEM (4*34816 + 128*132*4)
__global__ void __launch_bounds__(256, 1) gate_mma_kernel(const float* __restrict__ Wg,
                                                          const float* __restrict__ bg,
                                                          const float* __restrict__ gam,
                                                          const float* __restrict__ bet,
                                                          const float* __restrict__ X,
                                                          float* __restrict__ out) {
    extern __shared__ char smc[];
    __nv_bfloat16* sAh = (__nv_bfloat16*)smc;
    __nv_bfloat16* sAl = (__nv_bfloat16*)(smc + 34816);
    __nv_bfloat16* sWh = (__nv_bfloat16*)(smc + 69632);
    __nv_bfloat16* sWl = (__nv_bfloat16*)(smc + 104448);
    float*         sC  = (float*)(smc + 139264);   // [128][132]

    int t = threadIdx.x;
    int warp = t >> 5, lane = t & 31;
    int gq = lane >> 2, qq = lane & 3;
    int mb = (warp >> 1) * 32, nb = (warp & 1) * 64;
    int r0 = blockIdx.x * 128;

    float acc[2][8][4];
    #pragma unroll
    for (int mt = 0; mt < 2; mt++)
        #pragma unroll
        for (int nt = 0; nt < 8; nt++)
            #pragma unroll
            for (int r = 0; r < 4; r++) acc[mt][nt][r] = 0.f;

    #pragma unroll
    for (int half = 0; half < 2; half++) {
        if (half) __syncthreads();   // previous mma done before buffers overwritten
        load_tile_bf16(sAh, (half ? S_stru_h : S_feat_h) + (size_t)r0 * 128, t);
        load_tile_bf16(sAl, (half ? S_stru_l : S_feat_l) + (size_t)r0 * 128, t);
        load_w_split(sWh, sWl, Wg + half * 16384, t);
        __syncthreads();
        mma_pass(sAh, sWh, acc, mb, nb, gq, qq);
        mma_pass(sAh, sWl, acc, mb, nb, gq, qq);
        mma_pass(sAl, sWh, acc, mb, nb, gq, qq);
    }

    // dump z to smem
    #pragma unroll
    for (int mt = 0; mt < 2; mt++) {
        int row0 = mb + mt * 16 + gq;
        #pragma unroll
        for (int nt = 0; nt < 8; nt++) {
            int col = nb + nt * 8 + qq * 2;
            *(float2*)&sC[row0 * 132 + col] = make_float2(acc[mt][nt][0], acc[mt][nt][1]);
            *(float2*)&sC[(row0 + 8) * 132 + col] = make_float2(acc[mt][nt][2], acc[mt][nt][3]);
        }
    }
    __syncthreads();

    // epilogue: warp per row
    float4 b4 = *(const float4*)(bg + lane * 4);
    float4 gg = *(const float4*)(gam + lane * 4);
    float4 be = *(const float4*)(bet + lane * 4);
    for (int r = warp; r < 128; r += 8) {
        int gr = r0 + r;
        float4 z = *(float4*)&sC[r * 132 + lane * 4];
        float g0 = 1.0f / (1.0f + expf(-(z.x + b4.x)));
        float g1 = 1.0f / (1.0f + expf(-(z.y + b4.y)));
        float g2 = 1.0f / (1.0f + expf(-(z.z + b4.z)));
        float g3 = 1.0f / (1.0f + expf(-(z.w + b4.w)));
        float4 fv = *(const float4*)(S_feat + (size_t)gr * DIM + lane * 4);
        float4 sv = *(const float4*)(S_stru + (size_t)gr * DIM + lane * 4);
        float f0 = g0 * fv.x + (1.0f - g0) * sv.x;
        float f1 = g1 * fv.y + (1.0f - g1) * sv.y;
        float f2 = g2 * fv.z + (1.0f - g2) * sv.z;
        float f3 = g3 * fv.w + (1.0f - g3) * sv.w;
        float s1 = f0 + f1 + f2 + f3;
        #pragma unroll
        for (int o = 16; o > 0; o >>= 1) s1 += __shfl_xor_sync(0xffffffffu, s1, o);
        float mean = s1 * (1.0f / 128.0f);
        float d0 = f0 - mean, d1 = f1 - mean, d2 = f2 - mean, d3 = f3 - mean;
        float q = d0*d0 + d1*d1 + d2*d2 + d3*d3;
        #pragma unroll
        for (int o = 16; o > 0; o >>= 1) q += __shfl_xor_sync(0xffffffffu, q, o);
        float rstd = rsqrtf(q * (1.0f / 128.0f) + 1e-5f);
        float4 xr = *(const float4*)(X + (size_t)gr * DIM + lane * 4);
        float4 o4 = make_float4(d0*rstd*gg.x + be.x + xr.x,
                                d1*rstd*gg.y + be.y + xr.y,
                                d2*rstd*gg.z + be.z + xr.z,
                                d3*rstd*gg.w + be.w + xr.w);
        *(float4*)(out + (size_t)gr * DIM + lane * 4) = o4;
    }
}

// ---------------- launch ----------------
extern "C" void kernel_launch(void* const* d_in, const int* in_sizes, int n_in,
                              void* d_out, int out_size) {
    const float* x       = (const float*)d_in[0];
    const int*   eidx    = (const int*)d_in[1];
    const float* W_feat  = (const float*)d_in[2];
    const float* b_feat  = (const float*)d_in[3];
    const float* W_stru  = (const float*)d_in[4];
    const float* b_stru  = (const float*)d_in[5];
    const float* W_gate  = (const float*)d_in[6];
    const float* b_gate  = (const float*)d_in[7];
    const float* gm_feat = (const float*)d_in[8];
    const float* be_feat = (const float*)d_in[9];
    const float* gm_stru = (const float*)d_in[10];
    const float* be_stru = (const float*)d_in[11];
    const float* gm_fus  = (const float*)d_in[12];
    const float* be_fus  = (const float*)d_in[13];
    float* out = (float*)d_out;

    const int* e_src = eidx;
    const int* e_dst = eidx + EDGES;

    cudaFuncSetAttribute(topk_mma_kernel, cudaFuncAttributeMaxDynamicSharedMemorySize, TOPK_SMEM_BYTES);
    cudaFuncSetAttribute(xgemm_kernel,    cudaFuncAttributeMaxDynamicSharedMemorySize, XGEMM_SMEM);
    cudaFuncSetAttribute(gate_mma_kernel, cudaFuncAttributeMaxDynamicSharedMemorySize, GATE2_SMEM);

    float *p_hf, *p_hs, *p_feat, *p_stru, *p_dinv_s, *p_dinv_f;
    int *p_cnt_s, *p_off_s, *p_cnt_f, *p_off_f, *p_csr_s, *p_csr_f, *p_cur_s, *p_cur_f;
    __nv_bfloat16 *p_fh, *p_fl, *p_sh, *p_sl;
    cudaGetSymbolAddress((void**)&p_hf, S_hf);
    cudaGetSymbolAddress((void**)&p_hs, S_hs);
    cudaGetSymbolAddress((void**)&p_feat, S_feat);
    cudaGetSymbolAddress((void**)&p_stru, S_stru);
    cudaGetSymbolAddress((void**)&p_dinv_s, S_dinv_s);
    cudaGetSymbolAddress((void**)&p_dinv_f, S_dinv_f);
    cudaGetSymbolAddress((void**)&p_cnt_s, S_cnt_s);
    cudaGetSymbolAddress((void**)&p_off_s, S_off_s);
    cudaGetSymbolAddress((void**)&p_cnt_f, S_cnt_f);
    cudaGetSymbolAddress((void**)&p_off_f, S_off_f);
    cudaGetSymbolAddress((void**)&p_csr_s, S_csr_s);
    cudaGetSymbolAddress((void**)&p_csr_f, S_csr_f);
    cudaGetSymbolAddress((void**)&p_cur_s, S_cur_s);
    cudaGetSymbolAddress((void**)&p_cur_f, S_cur_f);
    cudaGetSymbolAddress((void**)&p_fh, S_feat_h);
    cudaGetSymbolAddress((void**)&p_fl, S_feat_l);
    cudaGetSymbolAddress((void**)&p_sh, S_stru_h);
    cudaGetSymbolAddress((void**)&p_sl, S_stru_l);

    zero_counts_kernel<<<NN/256, 256>>>();
    count_stru_kernel<<<EDGES/256, 256>>>(e_dst);
    split_kernel<<<NN/8, 256>>>(x);
    xgemm_kernel<<<NN/128, 256, XGEMM_SMEM>>>(W_feat, W_stru);
    topk_mma_kernel<<<NGRAPH*8, 256, TOPK_SMEM_BYTES>>>();   // 5th launch -> ncu slot
    scan_kernel<<<1, 1024>>>(p_cnt_s, p_off_s, p_cur_s);
    scan_kernel<<<1, 1024>>>(p_cnt_f, p_off_f, p_cur_f);
    scatter_stru_kernel<<<EDGES/256, 256>>>(e_src, e_dst);
    scatter_feat_kernel<<<FEDGES/256, 256>>>();
    dinv_kernel<<<NN/256, 256>>>();
    agg_ln_kernel<<<NN/8, 256>>>(p_hf, p_csr_f, p_off_f, p_cnt_f, p_dinv_f,
                                 b_feat, gm_feat, be_feat, p_feat, p_fh, p_fl);
    agg_ln_kernel<<<NN/8, 256>>>(p_hs, p_csr_s, p_off_s, p_cnt_s, p_dinv_s,
                                 b_stru, gm_stru, be_stru, p_stru, p_sh, p_sl);
    gate_mma_kernel<<<NN/128, 256, GATE2_SMEM>>>(W_gate, b_gate, gm_fus, be_fus, x, out);
    (void)in_sizes; (void)n_in; (void)out_size;
}

// round 13
// speedup vs baseline: 1.7116x; 1.1607x over previous
#include <cuda_runtime.h>
#include <cuda_bf16.h>
#include <cstdint>
#include <math.h>
#include <float.h>

#define NN      65536
#define NGRAPH  64
#define GN      1024
#define DIM     128
#define EDGES   2097152
#define FK      4
#define FEDGES  (NN*FK)

// ---------------- scratch (no allocations allowed) ----------------
__device__ float         S_xn[(size_t)NN*DIM];
__device__ __nv_bfloat16 S_xbf[(size_t)NN*DIM];
__device__ __nv_bfloat16 S_xh[(size_t)NN*DIM];
__device__ __nv_bfloat16 S_xl[(size_t)NN*DIM];
__device__ float S_hf[NN*DIM];
__device__ float S_hs[NN*DIM];
__device__ float S_feat[NN*DIM];
__device__ float S_stru[NN*DIM];
__device__ __nv_bfloat16 S_feat_h[(size_t)NN*DIM], S_feat_l[(size_t)NN*DIM];
__device__ __nv_bfloat16 S_stru_h[(size_t)NN*DIM], S_stru_l[(size_t)NN*DIM];
__device__ int   S_fdst[FEDGES];
__device__ int   S_cnt_s[NN], S_off_s[NN], S_cur_s[NN];
__device__ int   S_cnt_f[NN], S_off_f[NN], S_cur_f[NN];
__device__ float S_dinv_s[NN], S_dinv_f[NN];
__device__ int   S_csr_s[EDGES];
__device__ int   S_csr_f[FEDGES];

__device__ __forceinline__ bool cand_better(float da, int ja, float db, int jb) {
    return (da < db) || (da == db && ja < jb);
}

// ---------------- 0: zero counters ----------------
__global__ void zero_counts_kernel() {
    int i = blockIdx.x * blockDim.x + threadIdx.x;
    if (i < NN) { S_cnt_s[i] = 0; S_cnt_f[i] = 0; }
}

// ---------------- 1: structural in-degree ----------------
__global__ void count_stru_kernel(const int* __restrict__ dst) {
    int e = blockIdx.x * blockDim.x + threadIdx.x;
    if (e < EDGES) atomicAdd(&S_cnt_s[dst[e]], 1);
}

// ---------------- 2: normalize + raw-x bf16 hi/lo split ----------------
__global__ void split_kernel(const float* __restrict__ X) {
    int w = (blockIdx.x * blockDim.x + threadIdx.x) >> 5;
    int l = threadIdx.x & 31;
    if (w >= NN) return;
    float4 v = *(const float4*)(X + (size_t)w * DIM + l * 4);
    float raw[4] = {v.x, v.y, v.z, v.w};
    float ss = v.x*v.x + v.y*v.y + v.z*v.z + v.w*v.w;
    #pragma unroll
    for (int o = 16; o > 0; o >>= 1) ss += __shfl_xor_sync(0xffffffffu, ss, o);
    float inv = 1.0f / fmaxf(sqrtf(ss), 1e-8f);
    float xs[4] = {v.x*inv, v.y*inv, v.z*inv, v.w*inv};
    *(float4*)(S_xn + (size_t)w * DIM + l * 4) = make_float4(xs[0], xs[1], xs[2], xs[3]);
    __nv_bfloat16 nb[4], rh[4], rl[4];
    #pragma unroll
    for (int i = 0; i < 4; i++) {
        nb[i] = __float2bfloat16(xs[i]);
        rh[i] = __float2bfloat16(raw[i]);
        rl[i] = __float2bfloat16(raw[i] - __bfloat162float(rh[i]));
    }
    *(uint2*)(S_xbf + (size_t)w * DIM + l * 4) = *(uint2*)nb;
    *(uint2*)(S_xh  + (size_t)w * DIM + l * 4) = *(uint2*)rh;
    *(uint2*)(S_xl  + (size_t)w * DIM + l * 4) = *(uint2*)rl;
}

// ---------------- shared mma.sync machinery (512 threads, 8m x 2n warps) ----------------
#define SA_STRIDE 136

__device__ __forceinline__ void mma_bf16(float* c, uint32_t a0, uint32_t a1,
                                         uint32_t a2, uint32_t a3,
                                         uint32_t b0, uint32_t b1) {
    asm volatile(
        "mma.sync.aligned.m16n8k16.row.col.f32.bf16.bf16.f32 "
        "{%0,%1,%2,%3}, {%4,%5,%6,%7}, {%8,%9}, {%0,%1,%2,%3};"
        : "+f"(c[0]), "+f"(c[1]), "+f"(c[2]), "+f"(c[3])
        : "r"(a0), "r"(a1), "r"(a2), "r"(a3), "r"(b0), "r"(b1));
}

// warp tile 16x64: acc[nt][4]; full K=128
__device__ __forceinline__ void mma_pass16(const __nv_bfloat16* sA, const __nv_bfloat16* sB,
                                           float acc[8][4], int mb, int nb, int gq, int qq) {
    #pragma unroll
    for (int ks = 0; ks < 8; ks++) {
        uint32_t bf[8][2];
        #pragma unroll
        for (int nt = 0; nt < 8; nt++) {
            const __nv_bfloat16* bp = sB + (nb + nt * 8 + gq) * SA_STRIDE + ks * 16 + qq * 2;
            bf[nt][0] = *(const uint32_t*)bp;
            bf[nt][1] = *(const uint32_t*)(bp + 8);
        }
        const __nv_bfloat16* ap = sA + (mb + gq) * SA_STRIDE + ks * 16 + qq * 2;
        uint32_t a0 = *(const uint32_t*)ap;
        uint32_t a1 = *(const uint32_t*)(ap + 8 * SA_STRIDE);
        uint32_t a2 = *(const uint32_t*)(ap + 8);
        uint32_t a3 = *(const uint32_t*)(ap + 8 * SA_STRIDE + 8);
        #pragma unroll
        for (int nt = 0; nt < 8; nt++)
            mma_bf16(acc[nt], a0, a1, a2, a3, bf[nt][0], bf[nt][1]);
    }
}

__device__ __forceinline__ void load_tile_512(__nv_bfloat16* dst,
                                              const __nv_bfloat16* src, int t) {
    #pragma unroll
    for (int i = 0; i < 4; i++) {
        int v = t + i * 512;
        int r = v >> 4, sg = v & 15;
        uint4 d = *(const uint4*)(src + (size_t)r * 128 + sg * 8);
        *(uint4*)((char*)dst + r * (SA_STRIDE * 2) + sg * 16) = d;
    }
}

__device__ __forceinline__ void load_w_split_512(__nv_bfloat16* wh, __nv_bfloat16* wl,
                                                 const float* __restrict__ W, int t) {
    for (int idx = t; idx < 16384; idx += 512) {
        int k = idx >> 7, n = idx & 127;
        float v = W[idx];
        __nv_bfloat16 h = __float2bfloat16(v);
        __nv_bfloat16 l = __float2bfloat16(v - __bfloat162float(h));
        wh[n * SA_STRIDE + k] = h;
        wl[n * SA_STRIDE + k] = l;
    }
}

__device__ __forceinline__ void screen_insert(float* sv, int* si, float dv, int jl) {
    if (cand_better(dv, jl, sv[7], si[7])) {
        sv[7] = dv; si[7] = jl;
        #pragma unroll
        for (int r = 7; r >= 1; r--) {
            if (cand_better(sv[r], si[r], sv[r-1], si[r-1])) {
                float td = sv[r]; sv[r] = sv[r-1]; sv[r-1] = td;
                int   ti = si[r]; si[r] = si[r-1]; si[r-1] = ti;
            }
        }
    }
}

// ---------------- 3: topk — in-register screening, double-buffered B ----------------
#define TOPK2_SMEM (3*34816)
__global__ void __launch_bounds__(512, 1) topk_mma_kernel() {
    extern __shared__ char smc[];
    __nv_bfloat16* sA  = (__nv_bfloat16*)smc;
    __nv_bfloat16* sB0 = (__nv_bfloat16*)(smc + 34816);
    __nv_bfloat16* sB1 = (__nv_bfloat16*)(smc + 69632);

    int t = threadIdx.x;
    int g = blockIdx.x >> 3, it = blockIdx.x & 7;
    int warp = t >> 5, lane = t & 31;
    int gq = lane >> 2, qq = lane & 3;
    int warp_m = warp >> 1, warp_n = warp & 1;
    int mb = warp_m * 16, nb = warp_n * 64;
    const int gbase = g * GN;

    load_tile_512(sA, S_xbf + (size_t)(gbase + it * 128) * DIM, t);
    load_tile_512(sB0, S_xbf + (size_t)gbase * DIM, t);

    float sv[2][8]; int si[2][8];
    #pragma unroll
    for (int s = 0; s < 2; s++)
        #pragma unroll
        for (int r = 0; r < 8; r++) { sv[s][r] = FLT_MAX; si[s][r] = 0x7fffffff; }

    __syncthreads();

    for (int jc = 0; jc < 8; jc++) {
        const __nv_bfloat16* cur = (jc & 1) ? sB1 : sB0;
        __nv_bfloat16*       nxt = (jc & 1) ? sB0 : sB1;
        uint4 st[4];
        if (jc < 7) {
            const __nv_bfloat16* src = S_xbf + (size_t)(gbase + (jc + 1) * 128) * DIM;
            #pragma unroll
            for (int i = 0; i < 4; i++) {
                int v = t + i * 512;
                int r = v >> 4, sg = v & 15;
                st[i] = *(const uint4*)(src + (size_t)r * 128 + sg * 8);
            }
        }

        float acc[8][4];
        #pragma unroll
        for (int nt = 0; nt < 8; nt++)
            #pragma unroll
            for (int r = 0; r < 4; r++) acc[nt][r] = 0.f;

        mma_pass16(sA, cur, acc, mb, nb, gq, qq);

        #pragma unroll
        for (int nt = 0; nt < 8; nt++) {
            int col = jc * 128 + nb + nt * 8 + qq * 2;
            screen_insert(sv[0], si[0], acc[nt][0], col);
            screen_insert(sv[0], si[0], acc[nt][1], col + 1);
            screen_insert(sv[1], si[1], acc[nt][2], col);
            screen_insert(sv[1], si[1], acc[nt][3], col + 1);
        }

        if (jc < 7) {
            #pragma unroll
            for (int i = 0; i < 4; i++) {
                int v = t + i * 512;
                int r = v >> 4, sg = v & 15;
                *(uint4*)((char*)nxt + r * (SA_STRIDE * 2) + sg * 16) = st[i];
            }
        }
        __syncthreads();
    }

    // merge: 8 owner threads per row x top-8 -> 64 candidates/row
    float* MV = (float*)(smc + 34816);           // [128][64]
    int*   MI = (int*)(smc + 34816 + 32768);     // [128][64]
    int o = warp_n * 4 + qq;
    #pragma unroll
    for (int s = 0; s < 2; s++) {
        int row = mb + gq + s * 8;
        #pragma unroll
        for (int r = 0; r < 8; r++) {
            MV[row * 64 + o * 8 + r] = sv[s][r];
            MI[row * 64 + o * 8 + r] = si[s][r];
        }
    }
    __syncthreads();

    if (t < 128) {
        int row = t;
        float mv[8]; int mi[8];
        #pragma unroll
        for (int r = 0; r < 8; r++) { mv[r] = FLT_MAX; mi[r] = 0x7fffffff; }
        for (int c = 0; c < 64; c++)
            screen_insert(mv, mi, MV[row * 64 + c], MI[row * 64 + c]);

        int inode = gbase + it * 128 + row;
        const float* xi = S_xn + (size_t)inode * DIM;
        float t4d[4]; int t4i[4];
        #pragma unroll
        for (int r = 0; r < 4; r++) { t4d[r] = FLT_MAX; t4i[r] = 0x7fffffff; }
        #pragma unroll
        for (int c = 0; c < 8; c++) {
            int j = mi[c];
            const float* xj = S_xn + (size_t)(gbase + j) * DIM;
            float dot = 0.f;
            #pragma unroll 8
            for (int kk = 0; kk < 32; kk++) {
                float4 a = *(const float4*)(xi + kk * 4);
                float4 b = *(const float4*)(xj + kk * 4);
                dot += a.x*b.x + a.y*b.y + a.z*b.z + a.w*b.w;
            }
            if (cand_better(dot, j, t4d[3], t4i[3])) {
                t4d[3] = dot; t4i[3] = j;
                #pragma unroll
                for (int r = 3; r >= 1; r--) {
                    if (cand_better(t4d[r], t4i[r], t4d[r-1], t4i[r-1])) {
                        float td = t4d[r]; t4d[r] = t4d[r-1]; t4d[r-1] = td;
                        int   ti = t4i[r]; t4i[r] = t4i[r-1]; t4i[r-1] = ti;
                    }
                }
            }
        }
        #pragma unroll
        for (int r = 0; r < 4; r++) {
            int dg = gbase + t4i[r];
            S_fdst[inode * 4 + r] = dg;
            atomicAdd(&S_cnt_f[dg], 1);
        }
    }
}

// ---------------- 4: xgemm — both weights, bf16 3-term split ----------------
#define XGEMM_SMEM (4*34816)
__global__ void __launch_bounds__(512, 1) xgemm_kernel(const float* __restrict__ Wf,
                                                       const float* __restrict__ Ws) {
    extern __shared__ char smc[];
    __nv_bfloat16* sAh = (__nv_bfloat16*)smc;
    __nv_bfloat16* sAl = (__nv_bfloat16*)(smc + 34816);
    __nv_bfloat16* sWh = (__nv_bfloat16*)(smc + 69632);
    __nv_bfloat16* sWl = (__nv_bfloat16*)(smc + 104448);

    int t = threadIdx.x;
    int warp = t >> 5, lane = t & 31;
    int gq = lane >> 2, qq = lane & 3;
    int mb = (warp >> 1) * 16, nb = (warp & 1) * 64;
    int r0 = blockIdx.x * 128;

    load_tile_512(sAh, S_xh + (size_t)r0 * 128, t);
    load_tile_512(sAl, S_xl + (size_t)r0 * 128, t);

    #pragma unroll
    for (int wsel = 0; wsel < 2; wsel++) {
        load_w_split_512(sWh, sWl, wsel ? Ws : Wf, t);
        __syncthreads();

        float acc[8][4];
        #pragma unroll
        for (int nt = 0; nt < 8; nt++)
            #pragma unroll
            for (int r = 0; r < 4; r++) acc[nt][r] = 0.f;

        mma_pass16(sAh, sWh, acc, mb, nb, gq, qq);
        mma_pass16(sAh, sWl, acc, mb, nb, gq, qq);
        mma_pass16(sAl, sWh, acc, mb, nb, gq, qq);

        float* H = wsel ? S_hs : S_hf;
        int row0 = r0 + mb + gq;
        #pragma unroll
        for (int nt = 0; nt < 8; nt++) {
            int col = nb + nt * 8 + qq * 2;
            *(float2*)(H + (size_t)row0 * DIM + col) = make_float2(acc[nt][0], acc[nt][1]);
            *(float2*)(H + (size_t)(row0 + 8) * DIM + col) = make_float2(acc[nt][2], acc[nt][3]);
        }
        __syncthreads();
    }
}

// ---------------- 5: exclusive scan ----------------
__global__ void __launch_bounds__(1024, 1) scan_kernel(const int* __restrict__ cnt,
                                                       int* __restrict__ off,
                                                       int* __restrict__ cur) {
    __shared__ int wsum[32];
    int t = threadIdx.x;
    const int4* c4 = (const int4*)(cnt + t * 64);
    int s = 0;
    #pragma unroll
    for (int i = 0; i < 16; i++) {
        int4 v = c4[i];
        s += v.x + v.y + v.z + v.w;
    }
    int lane = t & 31, wid = t >> 5;
    int v = s;
    #pragma unroll
    for (int o = 1; o < 32; o <<= 1) {
        int u = __shfl_up_sync(0xffffffffu, v, o);
        if (lane >= o) v += u;
    }
    if (lane == 31) wsum[wid] = v;
    __syncthreads();
    if (wid == 0) {
        int w = wsum[lane];
        #pragma unroll
        for (int o = 1; o < 32; o <<= 1) {
            int u = __shfl_up_sync(0xffffffffu, w, o);
            if (lane >= o) w += u;
        }
        wsum[lane] = w;
    }
    __syncthreads();
    int run = v - s + (wid > 0 ? wsum[wid - 1] : 0);
    int4* o4 = (int4*)(off + t * 64);
    int4* u4 = (int4*)(cur + t * 64);
    #pragma unroll
    for (int i = 0; i < 16; i++) {
        int4 cv = c4[i];
        int4 ov;
        ov.x = run; run += cv.x;
        ov.y = run; run += cv.y;
        ov.z = run; run += cv.z;
        ov.w = run; run += cv.w;
        o4[i] = ov; u4[i] = ov;
    }
}

// ---------------- 6: scatter to CSR ----------------
__global__ void scatter_stru_kernel(const int* __restrict__ src, const int* __restrict__ dst) {
    int e = blockIdx.x * blockDim.x + threadIdx.x;
    if (e < EDGES) {
        int d = dst[e];
        int p = atomicAdd(&S_cur_s[d], 1);
        S_csr_s[p] = src[e];
    }
}
__global__ void scatter_feat_kernel() {
    int e = blockIdx.x * blockDim.x + threadIdx.x;
    if (e < FEDGES) {
        int d = S_fdst[e];
        int p = atomicAdd(&S_cur_f[d], 1);
        S_csr_f[p] = e >> 2;
    }
}

// ---------------- 7: dinv ----------------
__global__ void dinv_kernel() {
    int i = blockIdx.x * blockDim.x + threadIdx.x;
    if (i < NN) {
        S_dinv_s[i] = rsqrtf((float)(S_cnt_s[i] + 1));
        S_dinv_f[i] = rsqrtf((float)(S_cnt_f[i] + 1));
    }
}

// ---------------- 8: aggregate + bias + relu + LN (+ bf16 split out) ----------------
__global__ void agg_ln_kernel(const float* __restrict__ H, const int* __restrict__ csr,
                              const int* __restrict__ off, const int* __restrict__ cnt,
                              const float* __restrict__ dinv,
                              const float* __restrict__ bias, const float* __restrict__ gamma,
                              const float* __restrict__ beta, float* __restrict__ out,
                              __nv_bfloat16* __restrict__ outh,
                              __nv_bfloat16* __restrict__ outl) {
    int w = (blockIdx.x * blockDim.x + threadIdx.x) >> 5;
    int l = threadIdx.x & 31;
    if (w >= NN) return;
    float dv = dinv[w];
    float4 hv = *(const float4*)(H + (size_t)w * DIM + l * 4);
    float sw = dv * dv;
    float4 acc = make_float4(hv.x*sw, hv.y*sw, hv.z*sw, hv.w*sw);
    int base = off[w], n = cnt[w];
    int e = 0;
    for (; e + 3 < n; e += 4) {
        int s0 = csr[base + e],     s1 = csr[base + e + 1];
        int s2 = csr[base + e + 2], s3 = csr[base + e + 3];
        float w0 = dinv[s0] * dv, w1 = dinv[s1] * dv;
        float w2 = dinv[s2] * dv, w3 = dinv[s3] * dv;
        float4 h0 = *(const float4*)(H + (size_t)s0 * DIM + l * 4);
        float4 h1 = *(const float4*)(H + (size_t)s1 * DIM + l * 4);
        float4 h2 = *(const float4*)(H + (size_t)s2 * DIM + l * 4);
        float4 h3 = *(const float4*)(H + (size_t)s3 * DIM + l * 4);
        acc.x += w0*h0.x + w1*h1.x + w2*h2.x + w3*h3.x;
        acc.y += w0*h0.y + w1*h1.y + w2*h2.y + w3*h3.y;
        acc.z += w0*h0.z + w1*h1.z + w2*h2.z + w3*h3.z;
        acc.w += w0*h0.w + w1*h1.w + w2*h2.w + w3*h3.w;
    }
    for (; e < n; e++) {
        int s0 = csr[base + e];
        float w0 = dinv[s0] * dv;
        float4 h0 = *(const float4*)(H + (size_t)s0 * DIM + l * 4);
        acc.x += w0*h0.x; acc.y += w0*h0.y; acc.z += w0*h0.z; acc.w += w0*h0.w;
    }
    float4 bb = *(const float4*)(bias + l * 4);
    float v0 = fmaxf(acc.x + bb.x, 0.f);
    float v1 = fmaxf(acc.y + bb.y, 0.f);
    float v2 = fmaxf(acc.z + bb.z, 0.f);
    float v3 = fmaxf(acc.w + bb.w, 0.f);
    float s1 = v0 + v1 + v2 + v3;
    #pragma unroll
    for (int o = 16; o > 0; o >>= 1) s1 += __shfl_xor_sync(0xffffffffu, s1, o);
    float mean = s1 * (1.0f / 128.0f);
    float d0 = v0 - mean, d1 = v1 - mean, d2 = v2 - mean, d3 = v3 - mean;
    float q = d0*d0 + d1*d1 + d2*d2 + d3*d3;
    #pragma unroll
    for (int o = 16; o > 0; o >>= 1) q += __shfl_xor_sync(0xffffffffu, q, o);
    float rstd = rsqrtf(q * (1.0f / 128.0f) + 1e-5f);
    float4 gg = *(const float4*)(gamma + l * 4);
    float4 be = *(const float4*)(beta + l * 4);
    float4 o4 = make_float4(d0*rstd*gg.x + be.x, d1*rstd*gg.y + be.y,
                            d2*rstd*gg.z + be.z, d3*rstd*gg.w + be.w);
    *(float4*)(out + (size_t)w * DIM + l * 4) = o4;
    float ov[4] = {o4.x, o4.y, o4.z, o4.w};
    __nv_bfloat16 hh[4], ll[4];
    #pragma unroll
    for (int i = 0; i < 4; i++) {
        hh[i] = __float2bfloat16(ov[i]);
        ll[i] = __float2bfloat16(ov[i] - __bfloat162float(hh[i]));
    }
    *(uint2*)(outh + (size_t)w * DIM + l * 4) = *(uint2*)hh;
    *(uint2*)(outl + (size_t)w * DIM + l * 4) = *(uint2*)ll;
}

// ---------------- 9: gate GEMM + sigmoid + fuse + LN + residual ----------------
#define GATE2_SMEM (4*34816 + 128*132*4)
__global__ void __launch_bounds__(512, 1) gate_mma_kernel(const float* __restrict__ Wg,
                                                          const float* __restrict__ bg,
                                                          const float* __restrict__ gam,
                                                          const float* __restrict__ bet,
                                                          const float* __restrict__ X,
                                                          float* __restrict__ out) {
    extern __shared__ char smc[];
    __nv_bfloat16* sAh = (__nv_bfloat16*)smc;
    __nv_bfloat16* sAl = (__nv_bfloat16*)(smc + 34816);
    __nv_bfloat16* sWh = (__nv_bfloat16*)(smc + 69632);
    __nv_bfloat16* sWl = (__nv_bfloat16*)(smc + 104448);
    float*         sC  = (float*)(smc + 139264);   // [128][132]

    int t = threadIdx.x;
    int warp = t >> 5, lane = t & 31;
    int gq = lane >> 2, qq = lane & 3;
    int mb = (warp >> 1) * 16, nb = (warp & 1) * 64;
    int r0 = blockIdx.x * 128;

    float acc[8][4];
    #pragma unroll
    for (int nt = 0; nt < 8; nt++)
        #pragma unroll
        for (int r = 0; r < 4; r++) acc[nt][r] = 0.f;

    #pragma unroll
    for (int half = 0; half < 2; half++) {
        if (half) __syncthreads();
        load_tile_512(sAh, (half ? S_stru_h : S_feat_h) + (size_t)r0 * 128, t);
        load_tile_512(sAl, (half ? S_stru_l : S_feat_l) + (size_t)r0 * 128, t);
        load_w_split_512(sWh, sWl, Wg + half * 16384, t);
        __syncthreads();
        mma_pass16(sAh, sWh, acc, mb, nb, gq, qq);
        mma_pass16(sAh, sWl, acc, mb, nb, gq, qq);
        mma_pass16(sAl, sWh, acc, mb, nb, gq, qq);
    }

    int row0 = mb + gq;
    #pragma unroll
    for (int nt = 0; nt < 8; nt++) {
        int col = nb + nt * 8 + qq * 2;
        *(float2*)&sC[row0 * 132 + col] = make_float2(acc[nt][0], acc[nt][1]);
        *(float2*)&sC[(row0 + 8) * 132 + col] = make_float2(acc[nt][2], acc[nt][3]);
    }
    __syncthreads();

    float4 b4 = *(const float4*)(bg + lane * 4);
    float4 gg = *(const float4*)(gam + lane * 4);
    float4 be = *(const float4*)(bet + lane * 4);
    for (int r = warp; r < 128; r += 16) {
        int gr = r0 + r;
        float4 z = *(float4*)&sC[r * 132 + lane * 4];
        float g0 = 1.0f / (1.0f + expf(-(z.x + b4.x)));
        float g1 = 1.0f / (1.0f + expf(-(z.y + b4.y)));
        float g2 = 1.0f / (1.0f + expf(-(z.z + b4.z)));
        float g3 = 1.0f / (1.0f + expf(-(z.w + b4.w)));
        float4 fv = *(const float4*)(S_feat + (size_t)gr * DIM + lane * 4);
        float4 sv = *(const float4*)(S_stru + (size_t)gr * DIM + lane * 4);
        float f0 = g0 * fv.x + (1.0f - g0) * sv.x;
        float f1 = g1 * fv.y + (1.0f - g1) * sv.y;
        float f2 = g2 * fv.z + (1.0f - g2) * sv.z;
        float f3 = g3 * fv.w + (1.0f - g3) * sv.w;
        float s1 = f0 + f1 + f2 + f3;
        #pragma unroll
        for (int o = 16; o > 0; o >>= 1) s1 += __shfl_xor_sync(0xffffffffu, s1, o);
        float mean = s1 * (1.0f / 128.0f);
        float d0 = f0 - mean, d1 = f1 - mean, d2 = f2 - mean, d3 = f3 - mean;
        float q = d0*d0 + d1*d1 + d2*d2 + d3*d3;
        #pragma unroll
        for (int o = 16; o > 0; o >>= 1) q += __shfl_xor_sync(0xffffffffu, q, o);
        float rstd = rsqrtf(q * (1.0f / 128.0f) + 1e-5f);
        float4 xr = *(const float4*)(X + (size_t)gr * DIM + lane * 4);
        float4 o4 = make_float4(d0*rstd*gg.x + be.x + xr.x,
                                d1*rstd*gg.y + be.y + xr.y,
                                d2*rstd*gg.z + be.z + xr.z,
                                d3*rstd*gg.w + be.w + xr.w);
        *(float4*)(out + (size_t)gr * DIM + lane * 4) = o4;
    }
}

// ---------------- launch ----------------
extern "C" void kernel_launch(void* const* d_in, const int* in_sizes, int n_in,
                              void* d_out, int out_size) {
    const float* x       = (const float*)d_in[0];
    const int*   eidx    = (const int*)d_in[1];
    const float* W_feat  = (const float*)d_in[2];
    const float* b_feat  = (const float*)d_in[3];
    const float* W_stru  = (const float*)d_in[4];
    const float* b_stru  = (const float*)d_in[5];
    const float* W_gate  = (const float*)d_in[6];
    const float* b_gate  = (const float*)d_in[7];
    const float* gm_feat = (const float*)d_in[8];
    const float* be_feat = (const float*)d_in[9];
    const float* gm_stru = (const float*)d_in[10];
    const float* be_stru = (const float*)d_in[11];
    const float* gm_fus  = (const float*)d_in[12];
    const float* be_fus  = (const float*)d_in[13];
    float* out = (float*)d_out;

    const int* e_src = eidx;
    const int* e_dst = eidx + EDGES;

    cudaFuncSetAttribute(topk_mma_kernel, cudaFuncAttributeMaxDynamicSharedMemorySize, TOPK2_SMEM);
    cudaFuncSetAttribute(xgemm_kernel,    cudaFuncAttributeMaxDynamicSharedMemorySize, XGEMM_SMEM);
    cudaFuncSetAttribute(gate_mma_kernel, cudaFuncAttributeMaxDynamicSharedMemorySize, GATE2_SMEM);

    float *p_hf, *p_hs, *p_feat, *p_stru, *p_dinv_s, *p_dinv_f;
    int *p_cnt_s, *p_off_s, *p_cnt_f, *p_off_f, *p_csr_s, *p_csr_f, *p_cur_s, *p_cur_f;
    __nv_bfloat16 *p_fh, *p_fl, *p_sh, *p_sl;
    cudaGetSymbolAddress((void**)&p_hf, S_hf);
    cudaGetSymbolAddress((void**)&p_hs, S_hs);
    cudaGetSymbolAddress((void**)&p_feat, S_feat);
    cudaGetSymbolAddress((void**)&p_stru, S_stru);
    cudaGetSymbolAddress((void**)&p_dinv_s, S_dinv_s);
    cudaGetSymbolAddress((void**)&p_dinv_f, S_dinv_f);
    cudaGetSymbolAddress((void**)&p_cnt_s, S_cnt_s);
    cudaGetSymbolAddress((void**)&p_off_s, S_off_s);
    cudaGetSymbolAddress((void**)&p_cnt_f, S_cnt_f);
    cudaGetSymbolAddress((void**)&p_off_f, S_off_f);
    cudaGetSymbolAddress((void**)&p_csr_s, S_csr_s);
    cudaGetSymbolAddress((void**)&p_csr_f, S_csr_f);
    cudaGetSymbolAddress((void**)&p_cur_s, S_cur_s);
    cudaGetSymbolAddress((void**)&p_cur_f, S_cur_f);
    cudaGetSymbolAddress((void**)&p_fh, S_feat_h);
    cudaGetSymbolAddress((void**)&p_fl, S_feat_l);
    cudaGetSymbolAddress((void**)&p_sh, S_stru_h);
    cudaGetSymbolAddress((void**)&p_sl, S_stru_l);

    zero_counts_kernel<<<NN/256, 256>>>();
    count_stru_kernel<<<EDGES/256, 256>>>(e_dst);
    split_kernel<<<NN/8, 256>>>(x);
    topk_mma_kernel<<<NGRAPH*8, 512, TOPK2_SMEM>>>();        // 4th launch -> ncu slot
    xgemm_kernel<<<NN/128, 512, XGEMM_SMEM>>>(W_feat, W_stru);
    scan_kernel<<<1, 1024>>>(p_cnt_s, p_off_s, p_cur_s);
    scan_kernel<<<1, 1024>>>(p_cnt_f, p_off_f, p_cur_f);
    scatter_stru_kernel<<<EDGES/256, 256>>>(e_src, e_dst);
    scatter_feat_kernel<<<FEDGES/256, 256>>>();
    dinv_kernel<<<NN/256, 256>>>();
    agg_ln_kernel<<<NN/8, 256>>>(p_hf, p_csr_f, p_off_f, p_cnt_f, p_dinv_f,
                                 b_feat, gm_feat, be_feat, p_feat, p_fh, p_fl);
    agg_ln_kernel<<<NN/8, 256>>>(p_hs, p_csr_s, p_off_s, p_cnt_s, p_dinv_s,
                                 b_stru, gm_stru, be_stru, p_stru, p_sh, p_sl);
    gate_mma_kernel<<<NN/128, 512, GATE2_SMEM>>>(W_gate, b_gate, gm_fus, be_fus, x, out);
    (void)in_sizes; (void)n_in; (void)out_size;
}

// round 17
// speedup vs baseline: 2.2311x; 1.3035x over previous
#include <cuda_runtime.h>
#include <cuda_bf16.h>
#include <cstdint>
#include <math.h>
#include <float.h>

#define NN      65536
#define NGRAPH  64
#define GN      1024
#define DIM     128
#define EDGES   2097152
#define FK      4
#define FEDGES  (NN*FK)

// ---------------- scratch (no allocations allowed) ----------------
__device__ float         S_xn[(size_t)NN*DIM];
__device__ __nv_bfloat16 S_xbf[(size_t)NN*DIM];
__device__ __nv_bfloat16 S_xh[(size_t)NN*DIM];
__device__ __nv_bfloat16 S_xl[(size_t)NN*DIM];
__device__ float S_hf[NN*DIM];
__device__ float S_hs[NN*DIM];
__device__ float S_feat[NN*DIM];
__device__ float S_stru[NN*DIM];
__device__ __nv_bfloat16 S_feat_h[(size_t)NN*DIM], S_feat_l[(size_t)NN*DIM];
__device__ __nv_bfloat16 S_stru_h[(size_t)NN*DIM], S_stru_l[(size_t)NN*DIM];
__device__ int   S_fdst[FEDGES];
__device__ int   S_cnt_s[NN], S_off_s[NN], S_cur_s[NN];
__device__ int   S_cnt_f[NN], S_off_f[NN], S_cur_f[NN];
__device__ float S_dinv_s[NN], S_dinv_f[NN];
__device__ int   S_csr_s[EDGES];
__device__ int   S_csr_f[FEDGES];

__device__ __forceinline__ bool cand_better(float da, int ja, float db, int jb) {
    return (da < db) || (da == db && ja < jb);
}

// ---------------- 0: zero counters ----------------
__global__ void zero_counts_kernel() {
    int i = blockIdx.x * blockDim.x + threadIdx.x;
    if (i < NN) { S_cnt_s[i] = 0; S_cnt_f[i] = 0; }
}

// ---------------- 1: structural in-degree ----------------
__global__ void count_stru_kernel(const int* __restrict__ dst) {
    int e = blockIdx.x * blockDim.x + threadIdx.x;
    if (e < EDGES) atomicAdd(&S_cnt_s[dst[e]], 1);
}

// ---------------- 2: normalize + raw-x bf16 hi/lo split ----------------
__global__ void split_kernel(const float* __restrict__ X) {
    int w = (blockIdx.x * blockDim.x + threadIdx.x) >> 5;
    int l = threadIdx.x & 31;
    if (w >= NN) return;
    float4 v = *(const float4*)(X + (size_t)w * DIM + l * 4);
    float raw[4] = {v.x, v.y, v.z, v.w};
    float ss = v.x*v.x + v.y*v.y + v.z*v.z + v.w*v.w;
    #pragma unroll
    for (int o = 16; o > 0; o >>= 1) ss += __shfl_xor_sync(0xffffffffu, ss, o);
    float inv = 1.0f / fmaxf(sqrtf(ss), 1e-8f);
    float xs[4] = {v.x*inv, v.y*inv, v.z*inv, v.w*inv};
    *(float4*)(S_xn + (size_t)w * DIM + l * 4) = make_float4(xs[0], xs[1], xs[2], xs[3]);
    __nv_bfloat16 nb[4], rh[4], rl[4];
    #pragma unroll
    for (int i = 0; i < 4; i++) {
        nb[i] = __float2bfloat16(xs[i]);
        rh[i] = __float2bfloat16(raw[i]);
        rl[i] = __float2bfloat16(raw[i] - __bfloat162float(rh[i]));
    }
    *(uint2*)(S_xbf + (size_t)w * DIM + l * 4) = *(uint2*)nb;
    *(uint2*)(S_xh  + (size_t)w * DIM + l * 4) = *(uint2*)rh;
    *(uint2*)(S_xl  + (size_t)w * DIM + l * 4) = *(uint2*)rl;
}

// ---------------- shared mma.sync machinery (512 threads, 8m x 2n warps) ----------------
#define SA_STRIDE 136

__device__ __forceinline__ void mma_bf16(float* c, uint32_t a0, uint32_t a1,
                                         uint32_t a2, uint32_t a3,
                                         uint32_t b0, uint32_t b1) {
    asm volatile(
        "mma.sync.aligned.m16n8k16.row.col.f32.bf16.bf16.f32 "
        "{%0,%1,%2,%3}, {%4,%5,%6,%7}, {%8,%9}, {%0,%1,%2,%3};"
        : "+f"(c[0]), "+f"(c[1]), "+f"(c[2]), "+f"(c[3])
        : "r"(a0), "r"(a1), "r"(a2), "r"(a3), "r"(b0), "r"(b1));
}

// warp tile 16x64: acc[nt][4]; full K=128
__device__ __forceinline__ void mma_pass16(const __nv_bfloat16* sA, const __nv_bfloat16* sB,
                                           float acc[8][4], int mb, int nb, int gq, int qq) {
    #pragma unroll
    for (int ks = 0; ks < 8; ks++) {
        uint32_t bf[8][2];
        #pragma unroll
        for (int nt = 0; nt < 8; nt++) {
            const __nv_bfloat16* bp = sB + (nb + nt * 8 + gq) * SA_STRIDE + ks * 16 + qq * 2;
            bf[nt][0] = *(const uint32_t*)bp;
            bf[nt][1] = *(const uint32_t*)(bp + 8);
        }
        const __nv_bfloat16* ap = sA + (mb + gq) * SA_STRIDE + ks * 16 + qq * 2;
        uint32_t a0 = *(const uint32_t*)ap;
        uint32_t a1 = *(const uint32_t*)(ap + 8 * SA_STRIDE);
        uint32_t a2 = *(const uint32_t*)(ap + 8);
        uint32_t a3 = *(const uint32_t*)(ap + 8 * SA_STRIDE + 8);
        #pragma unroll
        for (int nt = 0; nt < 8; nt++)
            mma_bf16(acc[nt], a0, a1, a2, a3, bf[nt][0], bf[nt][1]);
    }
}

__device__ __forceinline__ void load_tile_512(__nv_bfloat16* dst,
                                              const __nv_bfloat16* src, int t) {
    #pragma unroll
    for (int i = 0; i < 4; i++) {
        int v = t + i * 512;
        int r = v >> 4, sg = v & 15;
        uint4 d = *(const uint4*)(src + (size_t)r * 128 + sg * 8);
        *(uint4*)((char*)dst + r * (SA_STRIDE * 2) + sg * 16) = d;
    }
}

__device__ __forceinline__ void load_w_split_512(__nv_bfloat16* wh, __nv_bfloat16* wl,
                                                 const float* __restrict__ W, int t) {
    for (int idx = t; idx < 16384; idx += 512) {
        int k = idx >> 7, n = idx & 127;
        float v = W[idx];
        __nv_bfloat16 h = __float2bfloat16(v);
        __nv_bfloat16 l = __float2bfloat16(v - __bfloat162float(h));
        wh[n * SA_STRIDE + k] = h;
        wl[n * SA_STRIDE + k] = l;
    }
}

// value-only insert; gate is strict < (exact tie rule restored in fp32 rescore)
__device__ __forceinline__ void screen_insert2(float* sv, int* si, float dv, int jl) {
    if (dv < sv[7]) {
        sv[7] = dv; si[7] = jl;
        #pragma unroll
        for (int r = 7; r >= 1; r--) {
            if (sv[r] < sv[r-1]) {
                float td = sv[r]; sv[r] = sv[r-1]; sv[r-1] = td;
                int   ti = si[r]; si[r] = si[r-1]; si[r-1] = ti;
            }
        }
    }
}

// ---------------- 3: topk — fast-gated screening + warp-parallel rescore ----------------
#define TOPK2_SMEM (3*34816)
__global__ void __launch_bounds__(512, 1) topk_mma_kernel() {
    extern __shared__ char smc[];
    __nv_bfloat16* sA  = (__nv_bfloat16*)smc;
    __nv_bfloat16* sB0 = (__nv_bfloat16*)(smc + 34816);
    __nv_bfloat16* sB1 = (__nv_bfloat16*)(smc + 69632);

    int t = threadIdx.x;
    int g = blockIdx.x >> 3, it = blockIdx.x & 7;
    int warp = t >> 5, lane = t & 31;
    int gq = lane >> 2, qq = lane & 3;
    int warp_m = warp >> 1, warp_n = warp & 1;
    int mb = warp_m * 16, nb = warp_n * 64;
    const int gbase = g * GN;

    load_tile_512(sA, S_xbf + (size_t)(gbase + it * 128) * DIM, t);
    load_tile_512(sB0, S_xbf + (size_t)gbase * DIM, t);

    float sv[2][8]; int si[2][8];
    #pragma unroll
    for (int s = 0; s < 2; s++)
        #pragma unroll
        for (int r = 0; r < 8; r++) { sv[s][r] = FLT_MAX; si[s][r] = 0x7fffffff; }

    __syncthreads();

    for (int jc = 0; jc < 8; jc++) {
        const __nv_bfloat16* cur = (jc & 1) ? sB1 : sB0;
        __nv_bfloat16*       nxt = (jc & 1) ? sB0 : sB1;
        uint4 st[4];
        if (jc < 7) {
            const __nv_bfloat16* src = S_xbf + (size_t)(gbase + (jc + 1) * 128) * DIM;
            #pragma unroll
            for (int i = 0; i < 4; i++) {
                int v = t + i * 512;
                int r = v >> 4, sg = v & 15;
                st[i] = *(const uint4*)(src + (size_t)r * 128 + sg * 8);
            }
        }

        float acc[8][4];
        #pragma unroll
        for (int nt = 0; nt < 8; nt++)
            #pragma unroll
            for (int r = 0; r < 4; r++) acc[nt][r] = 0.f;

        mma_pass16(sA, cur, acc, mb, nb, gq, qq);

        // fast-gated screening: one branch per (nt, row-set)
        #pragma unroll
        for (int nt = 0; nt < 8; nt++) {
            int col = jc * 128 + nb + nt * 8 + qq * 2;
            float m0 = fminf(acc[nt][0], acc[nt][1]);
            if (m0 < sv[0][7]) {
                screen_insert2(sv[0], si[0], acc[nt][0], col);
                screen_insert2(sv[0], si[0], acc[nt][1], col + 1);
            }
            float m1 = fminf(acc[nt][2], acc[nt][3]);
            if (m1 < sv[1][7]) {
                screen_insert2(sv[1], si[1], acc[nt][2], col);
                screen_insert2(sv[1], si[1], acc[nt][3], col + 1);
            }
        }

        if (jc < 7) {
            #pragma unroll
            for (int i = 0; i < 4; i++) {
                int v = t + i * 512;
                int r = v >> 4, sg = v & 15;
                *(uint4*)((char*)nxt + r * (SA_STRIDE * 2) + sg * 16) = st[i];
            }
        }
        __syncthreads();
    }

    // dump per-thread top-8 to smem: 8 owner threads per row
    float* MV  = (float*)(smc + 34816);           // [128][64]
    int*   MI  = (int*)(smc + 34816 + 32768);     // [128][64]
    int*   MI8 = (int*)smc;                       // [128][8] (aliases sA, done)
    int o = warp_n * 4 + qq;
    #pragma unroll
    for (int s = 0; s < 2; s++) {
        int row = mb + gq + s * 8;
        #pragma unroll
        for (int r = 0; r < 8; r++) {
            MV[row * 64 + o * 8 + r] = sv[s][r];
            MI[row * 64 + o * 8 + r] = si[s][r];
        }
    }
    __syncthreads();

    // merge 64 -> 8 per row (one thread per row)
    if (t < 128) {
        float mv[8]; int mi[8];
        #pragma unroll
        for (int r = 0; r < 8; r++) { mv[r] = FLT_MAX; mi[r] = 0x7fffffff; }
        for (int c = 0; c < 64; c++)
            screen_insert2(mv, mi, MV[t * 64 + c], MI[t * 64 + c]);
        #pragma unroll
        for (int r = 0; r < 8; r++) MI8[t * 8 + r] = mi[r];
    }
    __syncthreads();

    // warp-parallel exact fp32 rescore: 16 warps x 8 rows each
    for (int row = warp; row < 128; row += 16) {
        int inode = gbase + it * 128 + row;
        const float* xi = S_xn + (size_t)inode * DIM;
        float4 xa = *(const float4*)(xi + lane * 4);
        float t4d[4]; int t4i[4];
        #pragma unroll
        for (int r = 0; r < 4; r++) { t4d[r] = FLT_MAX; t4i[r] = 0x7fffffff; }
        #pragma unroll
        for (int c = 0; c < 8; c++) {
            int j = MI8[row * 8 + c];
            const float* xj = S_xn + (size_t)(gbase + j) * DIM;
            float4 xb = *(const float4*)(xj + lane * 4);
            float d = xa.x*xb.x + xa.y*xb.y + xa.z*xb.z + xa.w*xb.w;
            #pragma unroll
            for (int oo = 16; oo > 0; oo >>= 1) d += __shfl_xor_sync(0xffffffffu, d, oo);
            if (lane == 0) {
                if (cand_better(d, j, t4d[3], t4i[3])) {
                    t4d[3] = d; t4i[3] = j;
                    #pragma unroll
                    for (int r = 3; r >= 1; r--) {
                        if (cand_better(t4d[r], t4i[r], t4d[r-1], t4i[r-1])) {
                            float td = t4d[r]; t4d[r] = t4d[r-1]; t4d[r-1] = td;
                            int   ti = t4i[r]; t4i[r] = t4i[r-1]; t4i[r-1] = ti;
                        }
                    }
                }
            }
        }
        if (lane == 0) {
            #pragma unroll
            for (int r = 0; r < 4; r++) {
                int dg = gbase + t4i[r];
                S_fdst[inode * 4 + r] = dg;
                atomicAdd(&S_cnt_f[dg], 1);
            }
        }
    }
}

// ---------------- 4: xgemm — both weights, bf16 3-term split ----------------
#define XGEMM_SMEM (4*34816)
__global__ void __launch_bounds__(512, 1) xgemm_kernel(const float* __restrict__ Wf,
                                                       const float* __restrict__ Ws) {
    extern __shared__ char smc[];
    __nv_bfloat16* sAh = (__nv_bfloat16*)smc;
    __nv_bfloat16* sAl = (__nv_bfloat16*)(smc + 34816);
    __nv_bfloat16* sWh = (__nv_bfloat16*)(smc + 69632);
    __nv_bfloat16* sWl = (__nv_bfloat16*)(smc + 104448);

    int t = threadIdx.x;
    int warp = t >> 5, lane = t & 31;
    int gq = lane >> 2, qq = lane & 3;
    int mb = (warp >> 1) * 16, nb = (warp & 1) * 64;
    int r0 = blockIdx.x * 128;

    load_tile_512(sAh, S_xh + (size_t)r0 * 128, t);
    load_tile_512(sAl, S_xl + (size_t)r0 * 128, t);

    #pragma unroll
    for (int wsel = 0; wsel < 2; wsel++) {
        load_w_split_512(sWh, sWl, wsel ? Ws : Wf, t);
        __syncthreads();

        float acc[8][4];
        #pragma unroll
        for (int nt = 0; nt < 8; nt++)
            #pragma unroll
            for (int r = 0; r < 4; r++) acc[nt][r] = 0.f;

        mma_pass16(sAh, sWh, acc, mb, nb, gq, qq);
        mma_pass16(sAh, sWl, acc, mb, nb, gq, qq);
        mma_pass16(sAl, sWh, acc, mb, nb, gq, qq);

        float* H = wsel ? S_hs : S_hf;
        int row0 = r0 + mb + gq;
        #pragma unroll
        for (int nt = 0; nt < 8; nt++) {
            int col = nb + nt * 8 + qq * 2;
            *(float2*)(H + (size_t)row0 * DIM + col) = make_float2(acc[nt][0], acc[nt][1]);
            *(float2*)(H + (size_t)(row0 + 8) * DIM + col) = make_float2(acc[nt][2], acc[nt][3]);
        }
        __syncthreads();
    }
}

// ---------------- 5: exclusive scan ----------------
__global__ void __launch_bounds__(1024, 1) scan_kernel(const int* __restrict__ cnt,
                                                       int* __restrict__ off,
                                                       int* __restrict__ cur) {
    __shared__ int wsum[32];
    int t = threadIdx.x;
    const int4* c4 = (const int4*)(cnt + t * 64);
    int s = 0;
    #pragma unroll
    for (int i = 0; i < 16; i++) {
        int4 v = c4[i];
        s += v.x + v.y + v.z + v.w;
    }
    int lane = t & 31, wid = t >> 5;
    int v = s;
    #pragma unroll
    for (int o = 1; o < 32; o <<= 1) {
        int u = __shfl_up_sync(0xffffffffu, v, o);
        if (lane >= o) v += u;
    }
    if (lane == 31) wsum[wid] = v;
    __syncthreads();
    if (wid == 0) {
        int w = wsum[lane];
        #pragma unroll
        for (int o = 1; o < 32; o <<= 1) {
            int u = __shfl_up_sync(0xffffffffu, w, o);
            if (lane >= o) w += u;
        }
        wsum[lane] = w;
    }
    __syncthreads();
    int run = v - s + (wid > 0 ? wsum[wid - 1] : 0);
    int4* o4 = (int4*)(off + t * 64);
    int4* u4 = (int4*)(cur + t * 64);
    #pragma unroll
    for (int i = 0; i < 16; i++) {
        int4 cv = c4[i];
        int4 ov;
        ov.x = run; run += cv.x;
        ov.y = run; run += cv.y;
        ov.z = run; run += cv.z;
        ov.w = run; run += cv.w;
        o4[i] = ov; u4[i] = ov;
    }
}

// ---------------- 6: scatter to CSR ----------------
__global__ void scatter_stru_kernel(const int* __restrict__ src, const int* __restrict__ dst) {
    int e = blockIdx.x * blockDim.x + threadIdx.x;
    if (e < EDGES) {
        int d = dst[e];
        int p = atomicAdd(&S_cur_s[d], 1);
        S_csr_s[p] = src[e];
    }
}
__global__ void scatter_feat_kernel() {
    int e = blockIdx.x * blockDim.x + threadIdx.x;
    if (e < FEDGES) {
        int d = S_fdst[e];
        int p = atomicAdd(&S_cur_f[d], 1);
        S_csr_f[p] = e >> 2;
    }
}

// ---------------- 7: dinv ----------------
__global__ void dinv_kernel() {
    int i = blockIdx.x * blockDim.x + threadIdx.x;
    if (i < NN) {
        S_dinv_s[i] = rsqrtf((float)(S_cnt_s[i] + 1));
        S_dinv_f[i] = rsqrtf((float)(S_cnt_f[i] + 1));
    }
}

// ---------------- 8: aggregate + bias + relu + LN (+ bf16 split out) ----------------
__global__ void agg_ln_kernel(const float* __restrict__ H, const int* __restrict__ csr,
                              const int* __restrict__ off, const int* __restrict__ cnt,
                              const float* __restrict__ dinv,
                              const float* __restrict__ bias, const float* __restrict__ gamma,
                              const float* __restrict__ beta, float* __restrict__ out,
                              __nv_bfloat16* __restrict__ outh,
                              __nv_bfloat16* __restrict__ outl) {
    int w = (blockIdx.x * blockDim.x + threadIdx.x) >> 5;
    int l = threadIdx.x & 31;
    if (w >= NN) return;
    float dv = dinv[w];
    float4 hv = *(const float4*)(H + (size_t)w * DIM + l * 4);
    float sw = dv * dv;
    float4 acc = make_float4(hv.x*sw, hv.y*sw, hv.z*sw, hv.w*sw);
    int base = off[w], n = cnt[w];
    int e = 0;
    for (; e + 3 < n; e += 4) {
        int s0 = csr[base + e],     s1 = csr[base + e + 1];
        int s2 = csr[base + e + 2], s3 = csr[base + e + 3];
        float w0 = dinv[s0] * dv, w1 = dinv[s1] * dv;
        float w2 = dinv[s2] * dv, w3 = dinv[s3] * dv;
        float4 h0 = *(const float4*)(H + (size_t)s0 * DIM + l * 4);
        float4 h1 = *(const float4*)(H + (size_t)s1 * DIM + l * 4);
        float4 h2 = *(const float4*)(H + (size_t)s2 * DIM + l * 4);
        float4 h3 = *(const float4*)(H + (size_t)s3 * DIM + l * 4);
        acc.x += w0*h0.x + w1*h1.x + w2*h2.x + w3*h3.x;
        acc.y += w0*h0.y + w1*h1.y + w2*h2.y + w3*h3.y;
        acc.z += w0*h0.z + w1*h1.z + w2*h2.z + w3*h3.z;
        acc.w += w0*h0.w + w1*h1.w + w2*h2.w + w3*h3.w;
    }
    for (; e < n; e++) {
        int s0 = csr[base + e];
        float w0 = dinv[s0] * dv;
        float4 h0 = *(const float4*)(H + (size_t)s0 * DIM + l * 4);
        acc.x += w0*h0.x; acc.y += w0*h0.y; acc.z += w0*h0.z; acc.w += w0*h0.w;
    }
    float4 bb = *(const float4*)(bias + l * 4);
    float v0 = fmaxf(acc.x + bb.x, 0.f);
    float v1 = fmaxf(acc.y + bb.y, 0.f);
    float v2 = fmaxf(acc.z + bb.z, 0.f);
    float v3 = fmaxf(acc.w + bb.w, 0.f);
    float s1 = v0 + v1 + v2 + v3;
    #pragma unroll
    for (int o = 16; o > 0; o >>= 1) s1 += __shfl_xor_sync(0xffffffffu, s1, o);
    float mean = s1 * (1.0f / 128.0f);
    float d0 = v0 - mean, d1 = v1 - mean, d2 = v2 - mean, d3 = v3 - mean;
    float q = d0*d0 + d1*d1 + d2*d2 + d3*d3;
    #pragma unroll
    for (int o = 16; o > 0; o >>= 1) q += __shfl_xor_sync(0xffffffffu, q, o);
    float rstd = rsqrtf(q * (1.0f / 128.0f) + 1e-5f);
    float4 gg = *(const float4*)(gamma + l * 4);
    float4 be = *(const float4*)(beta + l * 4);
    float4 o4 = make_float4(d0*rstd*gg.x + be.x, d1*rstd*gg.y + be.y,
                            d2*rstd*gg.z + be.z, d3*rstd*gg.w + be.w);
    *(float4*)(out + (size_t)w * DIM + l * 4) = o4;
    float ov[4] = {o4.x, o4.y, o4.z, o4.w};
    __nv_bfloat16 hh[4], ll[4];
    #pragma unroll
    for (int i = 0; i < 4; i++) {
        hh[i] = __float2bfloat16(ov[i]);
        ll[i] = __float2bfloat16(ov[i] - __bfloat162float(hh[i]));
    }
    *(uint2*)(outh + (size_t)w * DIM + l * 4) = *(uint2*)hh;
    *(uint2*)(outl + (size_t)w * DIM + l * 4) = *(uint2*)ll;
}

// ---------------- 9: gate GEMM + sigmoid + fuse + LN + residual ----------------
#define GATE2_SMEM (4*34816 + 128*132*4)
__global__ void __launch_bounds__(512, 1) gate_mma_kernel(const float* __restrict__ Wg,
                                                          const float* __restrict__ bg,
                                                          const float* __restrict__ gam,
                                                          const float* __restrict__ bet,
                                                          const float* __restrict__ X,
                                                          float* __restrict__ out) {
    extern __shared__ char smc[];
    __nv_bfloat16* sAh = (__nv_bfloat16*)smc;
    __nv_bfloat16* sAl = (__nv_bfloat16*)(smc + 34816);
    __nv_bfloat16* sWh = (__nv_bfloat16*)(smc + 69632);
    __nv_bfloat16* sWl = (__nv_bfloat16*)(smc + 104448);
    float*         sC  = (float*)(smc + 139264);   // [128][132]

    int t = threadIdx.x;
    int warp = t >> 5, lane = t & 31;
    int gq = lane >> 2, qq = lane & 3;
    int mb = (warp >> 1) * 16, nb = (warp & 1) * 64;
    int r0 = blockIdx.x * 128;

    float acc[8][4];
    #pragma unroll
    for (int nt = 0; nt < 8; nt++)
        #pragma unroll
        for (int r = 0; r < 4; r++) acc[nt][r] = 0.f;

    #pragma unroll
    for (int half = 0; half < 2; half++) {
        if (half) __syncthreads();
        load_tile_512(sAh, (half ? S_stru_h : S_feat_h) + (size_t)r0 * 128, t);
        load_tile_512(sAl, (half ? S_stru_l : S_feat_l) + (size_t)r0 * 128, t);
        load_w_split_512(sWh, sWl, Wg + half * 16384, t);
        __syncthreads();
        mma_pass16(sAh, sWh, acc, mb, nb, gq, qq);
        mma_pass16(sAh, sWl, acc, mb, nb, gq, qq);
        mma_pass16(sAl, sWh, acc, mb, nb, gq, qq);
    }

    int row0 = mb + gq;
    #pragma unroll
    for (int nt = 0; nt < 8; nt++) {
        int col = nb + nt * 8 + qq * 2;
        *(float2*)&sC[row0 * 132 + col] = make_float2(acc[nt][0], acc[nt][1]);
        *(float2*)&sC[(row0 + 8) * 132 + col] = make_float2(acc[nt][2], acc[nt][3]);
    }
    __syncthreads();

    float4 b4 = *(const float4*)(bg + lane * 4);
    float4 gg = *(const float4*)(gam + lane * 4);
    float4 be = *(const float4*)(bet + lane * 4);
    for (int r = warp; r < 128; r += 16) {
        int gr = r0 + r;
        float4 z = *(float4*)&sC[r * 132 + lane * 4];
        float g0 = 1.0f / (1.0f + expf(-(z.x + b4.x)));
        float g1 = 1.0f / (1.0f + expf(-(z.y + b4.y)));
        float g2 = 1.0f / (1.0f + expf(-(z.z + b4.z)));
        float g3 = 1.0f / (1.0f + expf(-(z.w + b4.w)));
        float4 fv = *(const float4*)(S_feat + (size_t)gr * DIM + lane * 4);
        float4 sv = *(const float4*)(S_stru + (size_t)gr * DIM + lane * 4);
        float f0 = g0 * fv.x + (1.0f - g0) * sv.x;
        float f1 = g1 * fv.y + (1.0f - g1) * sv.y;
        float f2 = g2 * fv.z + (1.0f - g2) * sv.z;
        float f3 = g3 * fv.w + (1.0f - g3) * sv.w;
        float s1 = f0 + f1 + f2 + f3;
        #pragma unroll
        for (int o = 16; o > 0; o >>= 1) s1 += __shfl_xor_sync(0xffffffffu, s1, o);
        float mean = s1 * (1.0f / 128.0f);
        float d0 = f0 - mean, d1 = f1 - mean, d2 = f2 - mean, d3 = f3 - mean;
        float q = d0*d0 + d1*d1 + d2*d2 + d3*d3;
        #pragma unroll
        for (int o = 16; o > 0; o >>= 1) q += __shfl_xor_sync(0xffffffffu, q, o);
        float rstd = rsqrtf(q * (1.0f / 128.0f) + 1e-5f);
        float4 xr = *(const float4*)(X + (size_t)gr * DIM + lane * 4);
        float4 o4 = make_float4(d0*rstd*gg.x + be.x + xr.x,
                                d1*rstd*gg.y + be.y + xr.y,
                                d2*rstd*gg.z + be.z + xr.z,
                                d3*rstd*gg.w + be.w + xr.w);
        *(float4*)(out + (size_t)gr * DIM + lane * 4) = o4;
    }
}

// ---------------- launch ----------------
extern "C" void kernel_launch(void* const* d_in, const int* in_sizes, int n_in,
                              void* d_out, int out_size) {
    const float* x       = (const float*)d_in[0];
    const int*   eidx    = (const int*)d_in[1];
    const float* W_feat  = (const float*)d_in[2];
    const float* b_feat  = (const float*)d_in[3];
    const float* W_stru  = (const float*)d_in[4];
    const float* b_stru  = (const float*)d_in[5];
    const float* W_gate  = (const float*)d_in[6];
    const float* b_gate  = (const float*)d_in[7];
    const float* gm_feat = (const float*)d_in[8];
    const float* be_feat = (const float*)d_in[9];
    const float* gm_stru = (const float*)d_in[10];
    const float* be_stru = (const float*)d_in[11];
    const float* gm_fus  = (const float*)d_in[12];
    const float* be_fus  = (const float*)d_in[13];
    float* out = (float*)d_out;

    const int* e_src = eidx;
    const int* e_dst = eidx + EDGES;

    cudaFuncSetAttribute(topk_mma_kernel, cudaFuncAttributeMaxDynamicSharedMemorySize, TOPK2_SMEM);
    cudaFuncSetAttribute(xgemm_kernel,    cudaFuncAttributeMaxDynamicSharedMemorySize, XGEMM_SMEM);
    cudaFuncSetAttribute(gate_mma_kernel, cudaFuncAttributeMaxDynamicSharedMemorySize, GATE2_SMEM);

    float *p_hf, *p_hs, *p_feat, *p_stru, *p_dinv_s, *p_dinv_f;
    int *p_cnt_s, *p_off_s, *p_cnt_f, *p_off_f, *p_csr_s, *p_csr_f, *p_cur_s, *p_cur_f;
    __nv_bfloat16 *p_fh, *p_fl, *p_sh, *p_sl;
    cudaGetSymbolAddress((void**)&p_hf, S_hf);
    cudaGetSymbolAddress((void**)&p_hs, S_hs);
    cudaGetSymbolAddress((void**)&p_feat, S_feat);
    cudaGetSymbolAddress((void**)&p_stru, S_stru);
    cudaGetSymbolAddress((void**)&p_dinv_s, S_dinv_s);
    cudaGetSymbolAddress((void**)&p_dinv_f, S_dinv_f);
    cudaGetSymbolAddress((void**)&p_cnt_s, S_cnt_s);
    cudaGetSymbolAddress((void**)&p_off_s, S_off_s);
    cudaGetSymbolAddress((void**)&p_cnt_f, S_cnt_f);
    cudaGetSymbolAddress((void**)&p_off_f, S_off_f);
    cudaGetSymbolAddress((void**)&p_csr_s, S_csr_s);
    cudaGetSymbolAddress((void**)&p_csr_f, S_csr_f);
    cudaGetSymbolAddress((void**)&p_cur_s, S_cur_s);
    cudaGetSymbolAddress((void**)&p_cur_f, S_cur_f);
    cudaGetSymbolAddress((void**)&p_fh, S_feat_h);
    cudaGetSymbolAddress((void**)&p_fl, S_feat_l);
    cudaGetSymbolAddress((void**)&p_sh, S_stru_h);
    cudaGetSymbolAddress((void**)&p_sl, S_stru_l);

    zero_counts_kernel<<<NN/256, 256>>>();
    count_stru_kernel<<<EDGES/256, 256>>>(e_dst);
    split_kernel<<<NN/8, 256>>>(x);
    topk_mma_kernel<<<NGRAPH*8, 512, TOPK2_SMEM>>>();        // 4th launch -> ncu slot
    xgemm_kernel<<<NN/128, 512, XGEMM_SMEM>>>(W_feat, W_stru);
    scan_kernel<<<1, 1024>>>(p_cnt_s, p_off_s, p_cur_s);
    scan_kernel<<<1, 1024>>>(p_cnt_f, p_off_f, p_cur_f);
    scatter_stru_kernel<<<EDGES/256, 256>>>(e_src, e_dst);
    scatter_feat_kernel<<<FEDGES/256, 256>>>();
    dinv_kernel<<<NN/256, 256>>>();
    agg_ln_kernel<<<NN/8, 256>>>(p_hf, p_csr_f, p_off_f, p_cnt_f, p_dinv_f,
                                 b_feat, gm_feat, be_feat, p_feat, p_fh, p_fl);
    agg_ln_kernel<<<NN/8, 256>>>(p_hs, p_csr_s, p_off_s, p_cnt_s, p_dinv_s,
                                 b_stru, gm_stru, be_stru, p_stru, p_sh, p_sl);
    gate_mma_kernel<<<NN/128, 512, GATE2_SMEM>>>(W_gate, b_gate, gm_fus, be_fus, x, out);
    (void)in_sizes; (void)n_in; (void)out_size;
}